// round 5
// baseline (speedup 1.0000x reference)
#include <cuda_runtime.h>
#include <math.h>

// Problem constants (fixed by the dataset; runtime values checked against sizes)
#define MAXN 20000
#define NODE_DIM 128
#define EDGE_DIM 64
#define HID 128

// Scratch (device globals: no allocation allowed)
__device__ float g_aggr[(size_t)MAXN * HID];     // segment-summed edge messages
__device__ float g_cacc[(size_t)MAXN * 3];       // coord update accumulator

__device__ __forceinline__ float silu_f(float x) {
    return x / (1.0f + __expf(-x));
}

// ---------------------------------------------------------------------------
// zero scratch
// ---------------------------------------------------------------------------
__global__ void zero_kernel(int n_aggr, int n_coord) {
    int i = blockIdx.x * blockDim.x + threadIdx.x;
    if (i < n_aggr)  g_aggr[i] = 0.0f;
    if (i < n_coord) g_cacc[i] = 0.0f;
}

// ---------------------------------------------------------------------------
// Edge kernel: per 64-edge tile
//   in  = [x_src | x_dst | e_attr]  (320)
//   h1  = silu(in @ eW1 + eb1)      (128)
//   m   = silu(h1 @ eW2 + eb2)      (128)   -> atomicAdd into g_aggr[dst]
//   u   = silu(m @ cW1 + cb1)       (64)
//   w   = u @ cW2 + cb2             (1)     -> atomicAdd w*unit(coord diff) into g_cacc[dst]
// Thread block 256, register tile 4x8 over a 64x128 output tile.
// ---------------------------------------------------------------------------
__global__ __launch_bounds__(256, 2)
void edge_kernel(const float* __restrict__ node_feat,
                 const int*   __restrict__ esrc,
                 const int*   __restrict__ edst,
                 const float* __restrict__ edge_attr,
                 const float* __restrict__ coords,
                 const float* __restrict__ eW1, const float* __restrict__ eb1,
                 const float* __restrict__ eW2, const float* __restrict__ eb2,
                 const float* __restrict__ cW1, const float* __restrict__ cb1,
                 const float* __restrict__ cW2, const float* __restrict__ cb2,
                 int E)
{
    extern __shared__ float sm[];
    float* As = sm;                 // 64 x 33
    float* Bs = As + 64 * 33;       // 32 x 132
    float* Hs = Bs + 32 * 132;      // 64 x 132
    float* Ms = Hs + 64 * 132;      // 64 x 132
    int*   sidx = (int*)(Ms + 64 * 132);   // 64
    int*   didx = sidx + 64;               // 64

    const int tid = threadIdx.x;
    const int e0  = blockIdx.x * 64;
    const int tx  = tid & 15;   // 16 col groups
    const int ty  = tid >> 4;   // 16 row groups (4 rows each)

    if (tid < 64) {
        int e = e0 + tid;
        if (e >= E) e = E - 1;
        sidx[tid] = esrc[e];
        didx[tid] = edst[e];
    }
    __syncthreads();

    // ================= layer 1: [64,320] @ [320,128] =================
    float acc[4][8];
    #pragma unroll
    for (int i = 0; i < 4; i++)
        #pragma unroll
        for (int j = 0; j < 8; j++) acc[i][j] = 0.0f;

    for (int kt = 0; kt < 320; kt += 32) {
        // gather A tile (64 edges x 32 k)
        #pragma unroll
        for (int l = 0; l < 8; l++) {
            int idx = tid + l * 256;
            int e = idx >> 5, k = idx & 31;
            int g = kt + k;
            float v;
            if (g < 128) {
                v = node_feat[(size_t)sidx[e] * 128 + g];
            } else if (g < 256) {
                v = node_feat[(size_t)didx[e] * 128 + (g - 128)];
            } else {
                int ee = e0 + e; if (ee >= E) ee = E - 1;
                v = edge_attr[(size_t)ee * 64 + (g - 256)];
            }
            As[e * 33 + k] = v;
        }
        // load B tile (32 x 128) of eW1
        #pragma unroll
        for (int l = 0; l < 16; l++) {
            int idx = tid + l * 256;
            int k = idx >> 7, c = idx & 127;
            Bs[k * 132 + c] = eW1[(size_t)(kt + k) * 128 + c];
        }
        __syncthreads();
        #pragma unroll
        for (int k = 0; k < 32; k++) {
            float a[4], b[8];
            #pragma unroll
            for (int i = 0; i < 4; i++) a[i] = As[(ty * 4 + i) * 33 + k];
            #pragma unroll
            for (int j = 0; j < 8; j++) b[j] = Bs[k * 132 + tx + 16 * j];
            #pragma unroll
            for (int i = 0; i < 4; i++)
                #pragma unroll
                for (int j = 0; j < 8; j++) acc[i][j] += a[i] * b[j];
        }
        __syncthreads();
    }
    // h1 = silu(acc + eb1) -> Hs
    #pragma unroll
    for (int i = 0; i < 4; i++) {
        int r = ty * 4 + i;
        #pragma unroll
        for (int j = 0; j < 8; j++) {
            int c = tx + 16 * j;
            Hs[r * 132 + c] = silu_f(acc[i][j] + eb1[c]);
        }
    }
    __syncthreads();

    // ================= layer 2: [64,128] @ [128,128] =================
    #pragma unroll
    for (int i = 0; i < 4; i++)
        #pragma unroll
        for (int j = 0; j < 8; j++) acc[i][j] = 0.0f;

    for (int kt = 0; kt < 128; kt += 32) {
        #pragma unroll
        for (int l = 0; l < 16; l++) {
            int idx = tid + l * 256;
            int k = idx >> 7, c = idx & 127;
            Bs[k * 132 + c] = eW2[(size_t)(kt + k) * 128 + c];
        }
        __syncthreads();
        #pragma unroll
        for (int k = 0; k < 32; k++) {
            float a[4], b[8];
            #pragma unroll
            for (int i = 0; i < 4; i++) a[i] = Hs[(ty * 4 + i) * 132 + kt + k];
            #pragma unroll
            for (int j = 0; j < 8; j++) b[j] = Bs[k * 132 + tx + 16 * j];
            #pragma unroll
            for (int i = 0; i < 4; i++)
                #pragma unroll
                for (int j = 0; j < 8; j++) acc[i][j] += a[i] * b[j];
        }
        __syncthreads();
    }
    // m = silu(acc + eb2) -> Ms + atomic scatter to g_aggr[dst]
    #pragma unroll
    for (int i = 0; i < 4; i++) {
        int r = ty * 4 + i;
        bool ok = (e0 + r) < E;
        int d = didx[r];
        #pragma unroll
        for (int j = 0; j < 8; j++) {
            int c = tx + 16 * j;
            float m = silu_f(acc[i][j] + eb2[c]);
            Ms[r * 132 + c] = m;
            if (ok) atomicAdd(&g_aggr[(size_t)d * 128 + c], m);
        }
    }
    __syncthreads();

    // ================= coord mlp L1: u = silu(M @ cW1 + cb1) [64x64] ==========
    float acc3[4][4];
    #pragma unroll
    for (int i = 0; i < 4; i++)
        #pragma unroll
        for (int j = 0; j < 4; j++) acc3[i][j] = 0.0f;

    for (int kt = 0; kt < 128; kt += 32) {
        #pragma unroll
        for (int l = 0; l < 8; l++) {
            int idx = tid + l * 256;
            int k = idx >> 6, c = idx & 63;
            Bs[k * 132 + c] = cW1[(size_t)(kt + k) * 64 + c];
        }
        __syncthreads();
        #pragma unroll
        for (int k = 0; k < 32; k++) {
            float a[4], b[4];
            #pragma unroll
            for (int i = 0; i < 4; i++) a[i] = Ms[(ty * 4 + i) * 132 + kt + k];
            #pragma unroll
            for (int j = 0; j < 4; j++) b[j] = Bs[k * 132 + tx + 16 * j];
            #pragma unroll
            for (int i = 0; i < 4; i++)
                #pragma unroll
                for (int j = 0; j < 4; j++) acc3[i][j] += a[i] * b[j];
        }
        __syncthreads();
    }
    // store u into Hs (reuse)
    #pragma unroll
    for (int i = 0; i < 4; i++) {
        int r = ty * 4 + i;
        #pragma unroll
        for (int j = 0; j < 4; j++) {
            int c = tx + 16 * j;
            Hs[r * 132 + c] = silu_f(acc3[i][j] + cb1[c]);
        }
    }
    __syncthreads();

    // ================= w = u @ cW2 + cb2 ; coord scatter ==========
    if (tid < 64) {
        int r = tid;
        float w = cb2[0];
        #pragma unroll
        for (int j = 0; j < 64; j++) w += Hs[r * 132 + j] * cW2[j];
        if (e0 + r < E) {
            int s = sidx[r], d = didx[r];
            float dx = coords[(size_t)s * 3 + 0] - coords[(size_t)d * 3 + 0];
            float dy = coords[(size_t)s * 3 + 1] - coords[(size_t)d * 3 + 1];
            float dz = coords[(size_t)s * 3 + 2] - coords[(size_t)d * 3 + 2];
            float nrm = sqrtf(dx * dx + dy * dy + dz * dz) + 1e-8f;
            float scl = w / nrm;
            atomicAdd(&g_cacc[(size_t)d * 3 + 0], dx * scl);
            atomicAdd(&g_cacc[(size_t)d * 3 + 1], dy * scl);
            atomicAdd(&g_cacc[(size_t)d * 3 + 2], dz * scl);
        }
    }
}

// ---------------------------------------------------------------------------
// Node kernel: per 64-node tile
//   in  = [x | aggr]                     (256)
//   h   = silu(in @ nW1 + nb1)           (128)
//   out = x + h @ nW2 + nb2              (128)
//   out_coords = coords + g_cacc
// ---------------------------------------------------------------------------
__global__ __launch_bounds__(256, 3)
void node_kernel(const float* __restrict__ node_feat,
                 const float* __restrict__ coords,
                 const float* __restrict__ nW1, const float* __restrict__ nb1,
                 const float* __restrict__ nW2, const float* __restrict__ nb2,
                 float* __restrict__ out_nodes,
                 float* __restrict__ out_coords,
                 int N)
{
    extern __shared__ float sm[];
    float* As = sm;               // 64 x 33
    float* Bs = As + 64 * 33;     // 32 x 132
    float* Hs = Bs + 32 * 132;    // 64 x 132

    const int tid = threadIdx.x;
    const int n0  = blockIdx.x * 64;
    const int tx  = tid & 15;
    const int ty  = tid >> 4;

    float acc[4][8];
    #pragma unroll
    for (int i = 0; i < 4; i++)
        #pragma unroll
        for (int j = 0; j < 8; j++) acc[i][j] = 0.0f;

    // layer 1: [64,256] @ [256,128]
    for (int kt = 0; kt < 256; kt += 32) {
        #pragma unroll
        for (int l = 0; l < 8; l++) {
            int idx = tid + l * 256;
            int e = idx >> 5, k = idx & 31;
            int n = n0 + e; if (n >= N) n = N - 1;
            int g = kt + k;
            float v = (g < 128) ? node_feat[(size_t)n * 128 + g]
                                : g_aggr[(size_t)n * 128 + (g - 128)];
            As[e * 33 + k] = v;
        }
        #pragma unroll
        for (int l = 0; l < 16; l++) {
            int idx = tid + l * 256;
            int k = idx >> 7, c = idx & 127;
            Bs[k * 132 + c] = nW1[(size_t)(kt + k) * 128 + c];
        }
        __syncthreads();
        #pragma unroll
        for (int k = 0; k < 32; k++) {
            float a[4], b[8];
            #pragma unroll
            for (int i = 0; i < 4; i++) a[i] = As[(ty * 4 + i) * 33 + k];
            #pragma unroll
            for (int j = 0; j < 8; j++) b[j] = Bs[k * 132 + tx + 16 * j];
            #pragma unroll
            for (int i = 0; i < 4; i++)
                #pragma unroll
                for (int j = 0; j < 8; j++) acc[i][j] += a[i] * b[j];
        }
        __syncthreads();
    }
    #pragma unroll
    for (int i = 0; i < 4; i++) {
        int r = ty * 4 + i;
        #pragma unroll
        for (int j = 0; j < 8; j++) {
            int c = tx + 16 * j;
            Hs[r * 132 + c] = silu_f(acc[i][j] + nb1[c]);
        }
    }
    __syncthreads();

    // layer 2: [64,128] @ [128,128]
    #pragma unroll
    for (int i = 0; i < 4; i++)
        #pragma unroll
        for (int j = 0; j < 8; j++) acc[i][j] = 0.0f;

    for (int kt = 0; kt < 128; kt += 32) {
        #pragma unroll
        for (int l = 0; l < 16; l++) {
            int idx = tid + l * 256;
            int k = idx >> 7, c = idx & 127;
            Bs[k * 132 + c] = nW2[(size_t)(kt + k) * 128 + c];
        }
        __syncthreads();
        #pragma unroll
        for (int k = 0; k < 32; k++) {
            float a[4], b[8];
            #pragma unroll
            for (int i = 0; i < 4; i++) a[i] = Hs[(ty * 4 + i) * 132 + kt + k];
            #pragma unroll
            for (int j = 0; j < 8; j++) b[j] = Bs[k * 132 + tx + 16 * j];
            #pragma unroll
            for (int i = 0; i < 4; i++)
                #pragma unroll
                for (int j = 0; j < 8; j++) acc[i][j] += a[i] * b[j];
        }
        __syncthreads();
    }
    // residual write
    #pragma unroll
    for (int i = 0; i < 4; i++) {
        int r = ty * 4 + i;
        int n = n0 + r;
        if (n < N) {
            #pragma unroll
            for (int j = 0; j < 8; j++) {
                int c = tx + 16 * j;
                out_nodes[(size_t)n * 128 + c] =
                    node_feat[(size_t)n * 128 + c] + acc[i][j] + nb2[c];
            }
        }
    }
    // coords
    if (tid < 192) {
        int e = tid / 3, d = tid % 3;
        int n = n0 + e;
        if (n < N)
            out_coords[(size_t)n * 3 + d] =
                coords[(size_t)n * 3 + d] + g_cacc[(size_t)n * 3 + d];
    }
}

// ---------------------------------------------------------------------------
extern "C" void kernel_launch(void* const* d_in, const int* in_sizes, int n_in,
                              void* d_out, int out_size)
{
    const float* node_feat = (const float*)d_in[0];
    const int*   eidx      = (const int*)  d_in[1];
    const float* edge_attr = (const float*)d_in[2];
    const float* coords    = (const float*)d_in[3];
    const float* eW1 = (const float*)d_in[4];
    const float* eb1 = (const float*)d_in[5];
    const float* eW2 = (const float*)d_in[6];
    const float* eb2 = (const float*)d_in[7];
    const float* nW1 = (const float*)d_in[8];
    const float* nb1 = (const float*)d_in[9];
    const float* nW2 = (const float*)d_in[10];
    const float* nb2 = (const float*)d_in[11];
    const float* cW1 = (const float*)d_in[12];
    const float* cb1 = (const float*)d_in[13];
    const float* cW2 = (const float*)d_in[14];
    const float* cb2 = (const float*)d_in[15];

    const int N = in_sizes[0] / NODE_DIM;
    const int E = in_sizes[1] / 2;
    const int* esrc = eidx;
    const int* edst = eidx + E;

    float* out_nodes  = (float*)d_out;
    float* out_coords = out_nodes + (size_t)N * NODE_DIM;

    constexpr int EDGE_SMEM = (64 * 33 + 32 * 132 + 2 * 64 * 132) * 4 + 128 * 4; // 93,440 B
    constexpr int NODE_SMEM = (64 * 33 + 32 * 132 + 64 * 132) * 4;               // 59,136 B
    cudaFuncSetAttribute(edge_kernel, cudaFuncAttributeMaxDynamicSharedMemorySize, EDGE_SMEM);
    cudaFuncSetAttribute(node_kernel, cudaFuncAttributeMaxDynamicSharedMemorySize, NODE_SMEM);

    int zero_elems = N * HID;               // coord count (N*3) is < this
    zero_kernel<<<(zero_elems + 255) / 256, 256>>>(N * HID, N * 3);

    edge_kernel<<<(E + 63) / 64, 256, EDGE_SMEM>>>(
        node_feat, esrc, edst, edge_attr, coords,
        eW1, eb1, eW2, eb2, cW1, cb1, cW2, cb2, E);

    node_kernel<<<(N + 63) / 64, 256, NODE_SMEM>>>(
        node_feat, coords, nW1, nb1, nW2, nb2, out_nodes, out_coords, N);
}

// round 6
// speedup vs baseline: 1.6780x; 1.6780x over previous
#include <cuda_runtime.h>
#include <math.h>

// Problem constants (fixed by the dataset)
#define MAXN 20000
#define NODE_DIM 128
#define EDGE_DIM 64
#define HID 128

// Scratch (device globals: no allocation allowed)
__device__ float g_aggr[(size_t)MAXN * HID];     // segment-summed edge messages (full fp32)
__device__ float g_cacc[(size_t)MAXN * 3];       // coord update accumulator

__device__ __forceinline__ float silu_f(float x) {
    return x / (1.0f + __expf(-x));
}

__device__ __forceinline__ unsigned f2tf(float x) {
    unsigned r;
    asm("cvt.rna.tf32.f32 %0, %1;" : "=r"(r) : "f"(x));
    return r;
}

__device__ __forceinline__ void mma_tf32(float* c,
                                         unsigned a0, unsigned a1, unsigned a2, unsigned a3,
                                         unsigned b0, unsigned b1) {
    asm volatile("mma.sync.aligned.m16n8k8.row.col.f32.tf32.tf32.f32 "
                 "{%0,%1,%2,%3}, {%4,%5,%6,%7}, {%8,%9}, {%0,%1,%2,%3};"
                 : "+f"(c[0]), "+f"(c[1]), "+f"(c[2]), "+f"(c[3])
                 : "r"(a0), "r"(a1), "r"(a2), "r"(a3), "r"(b0), "r"(b1));
}

// ---------------------------------------------------------------------------
__global__ void zero_kernel(int n_aggr, int n_coord) {
    int i = blockIdx.x * blockDim.x + threadIdx.x;
    if (i < n_aggr)  g_aggr[i] = 0.0f;
    if (i < n_coord) g_cacc[i] = 0.0f;
}

// ---------------------------------------------------------------------------
// Edge kernel: 64-edge tile, tf32 tensor-core GEMMs.
//   in  = [x_src | x_dst | e_attr]  (320)
//   h1  = silu(in @ eW1 + eb1)      (128)
//   m   = silu(h1 @ eW2 + eb2)      (128)   -> atomicAdd fp32 into g_aggr[dst]
//   u   = silu(m @ cW1 + cb1)       (64)
//   w   = u @ cW2 + cb2             (1)     -> atomicAdd w*unit(diff) into g_cacc[dst]
// 8 warps: warp grid 4 (M) x 2 (N). Warp tile 16x64 (m16n8k8 fragments).
// Shared strides: A-side 36/132 (== 4 mod 32), B-side 136 (== 8 mod 32):
// all MMA fragment LDS are bank-conflict-free.
// ---------------------------------------------------------------------------
__global__ __launch_bounds__(256, 2)
void edge_kernel(const float* __restrict__ node_feat,
                 const int*   __restrict__ esrc,
                 const int*   __restrict__ edst,
                 const float* __restrict__ edge_attr,
                 const float* __restrict__ coords,
                 const float* __restrict__ eW1, const float* __restrict__ eb1,
                 const float* __restrict__ eW2, const float* __restrict__ eb2,
                 const float* __restrict__ cW1, const float* __restrict__ cb1,
                 const float* __restrict__ cW2, const float* __restrict__ cb2,
                 int E)
{
    extern __shared__ unsigned smu[];
    unsigned* As = smu;               // 64 x 36  (A tile, tf32)
    unsigned* Bs = As + 64 * 36;      // 32 x 136 (B tile, tf32)
    unsigned* Hs = Bs + 32 * 136;     // 64 x 132 (h1, tf32; later u fp32-bits)
    unsigned* Ms = Hs + 64 * 132;     // 64 x 132 (message, tf32)
    int* sidx = (int*)(Ms + 64 * 132);
    int* didx = sidx + 64;

    const int tid  = threadIdx.x;
    const int e0   = blockIdx.x * 64;
    const int lane = tid & 31;
    const int wid  = tid >> 5;
    const int g    = lane >> 2;   // groupID (0..7)
    const int tig  = lane & 3;    // thread-in-group (0..3)
    const int wm   = wid & 3;     // warp row (16 rows each)
    const int wn   = wid >> 2;    // warp col (64 cols each)

    if (tid < 64) {
        int e = e0 + tid; if (e >= E) e = E - 1;
        sidx[tid] = esrc[e];
        didx[tid] = edst[e];
    }
    __syncthreads();

    float c[8][4];
    #pragma unroll
    for (int i = 0; i < 8; i++)
        #pragma unroll
        for (int j = 0; j < 4; j++) c[i][j] = 0.0f;

    // ================= layer 1: [64,320] @ [320,128] =================
    for (int kt = 0; kt < 320; kt += 32) {
        #pragma unroll
        for (int l = 0; l < 8; l++) {
            int idx = tid + l * 256;
            int e = idx >> 5, k = idx & 31;
            int gg = kt + k;
            float v;
            if (gg < 128) {
                v = node_feat[(size_t)sidx[e] * 128 + gg];
            } else if (gg < 256) {
                v = node_feat[(size_t)didx[e] * 128 + (gg - 128)];
            } else {
                int ee = e0 + e; if (ee >= E) ee = E - 1;
                v = edge_attr[(size_t)ee * 64 + (gg - 256)];
            }
            As[e * 36 + k] = f2tf(v);
        }
        #pragma unroll
        for (int l = 0; l < 16; l++) {
            int idx = tid + l * 256;
            int k = idx >> 7, cc = idx & 127;
            Bs[k * 136 + cc] = f2tf(eW1[(size_t)(kt + k) * 128 + cc]);
        }
        __syncthreads();
        #pragma unroll
        for (int ks = 0; ks < 4; ks++) {
            int k0 = ks * 8;
            unsigned a0 = As[(wm * 16 + g) * 36 + k0 + tig];
            unsigned a1 = As[(wm * 16 + g + 8) * 36 + k0 + tig];
            unsigned a2 = As[(wm * 16 + g) * 36 + k0 + tig + 4];
            unsigned a3 = As[(wm * 16 + g + 8) * 36 + k0 + tig + 4];
            #pragma unroll
            for (int nt = 0; nt < 8; nt++) {
                int ncol = wn * 64 + nt * 8 + g;
                unsigned b0 = Bs[(k0 + tig) * 136 + ncol];
                unsigned b1 = Bs[(k0 + tig + 4) * 136 + ncol];
                mma_tf32(c[nt], a0, a1, a2, a3, b0, b1);
            }
        }
        __syncthreads();
    }
    // h1 = silu(c + eb1) -> Hs (tf32)
    #pragma unroll
    for (int nt = 0; nt < 8; nt++) {
        int col = wn * 64 + nt * 8 + 2 * tig;
        int r = wm * 16 + g;
        float b0v = eb1[col], b1v = eb1[col + 1];
        Hs[r * 132 + col]           = f2tf(silu_f(c[nt][0] + b0v));
        Hs[r * 132 + col + 1]       = f2tf(silu_f(c[nt][1] + b1v));
        Hs[(r + 8) * 132 + col]     = f2tf(silu_f(c[nt][2] + b0v));
        Hs[(r + 8) * 132 + col + 1] = f2tf(silu_f(c[nt][3] + b1v));
    }
    __syncthreads();

    // ================= layer 2: [64,128] @ [128,128] =================
    #pragma unroll
    for (int i = 0; i < 8; i++)
        #pragma unroll
        for (int j = 0; j < 4; j++) c[i][j] = 0.0f;

    for (int kt = 0; kt < 128; kt += 32) {
        #pragma unroll
        for (int l = 0; l < 16; l++) {
            int idx = tid + l * 256;
            int k = idx >> 7, cc = idx & 127;
            Bs[k * 136 + cc] = f2tf(eW2[(size_t)(kt + k) * 128 + cc]);
        }
        __syncthreads();
        #pragma unroll
        for (int ks = 0; ks < 4; ks++) {
            int k0 = ks * 8;
            int kg = kt + k0;
            unsigned a0 = Hs[(wm * 16 + g) * 132 + kg + tig];
            unsigned a1 = Hs[(wm * 16 + g + 8) * 132 + kg + tig];
            unsigned a2 = Hs[(wm * 16 + g) * 132 + kg + tig + 4];
            unsigned a3 = Hs[(wm * 16 + g + 8) * 132 + kg + tig + 4];
            #pragma unroll
            for (int nt = 0; nt < 8; nt++) {
                int ncol = wn * 64 + nt * 8 + g;
                unsigned b0 = Bs[(k0 + tig) * 136 + ncol];
                unsigned b1 = Bs[(k0 + tig + 4) * 136 + ncol];
                mma_tf32(c[nt], a0, a1, a2, a3, b0, b1);
            }
        }
        __syncthreads();
    }
    // m = silu(c + eb2): scatter full fp32 to g_aggr, store tf32 in Ms
    #pragma unroll
    for (int nt = 0; nt < 8; nt++) {
        int col = wn * 64 + nt * 8 + 2 * tig;
        int r = wm * 16 + g;
        float b0v = eb2[col], b1v = eb2[col + 1];
        float m00 = silu_f(c[nt][0] + b0v), m01 = silu_f(c[nt][1] + b1v);
        float m10 = silu_f(c[nt][2] + b0v), m11 = silu_f(c[nt][3] + b1v);
        Ms[r * 132 + col]           = f2tf(m00);
        Ms[r * 132 + col + 1]       = f2tf(m01);
        Ms[(r + 8) * 132 + col]     = f2tf(m10);
        Ms[(r + 8) * 132 + col + 1] = f2tf(m11);
        if (e0 + r < E) {
            int d = didx[r];
            atomicAdd(&g_aggr[(size_t)d * 128 + col],     m00);
            atomicAdd(&g_aggr[(size_t)d * 128 + col + 1], m01);
        }
        if (e0 + r + 8 < E) {
            int d = didx[r + 8];
            atomicAdd(&g_aggr[(size_t)d * 128 + col],     m10);
            atomicAdd(&g_aggr[(size_t)d * 128 + col + 1], m11);
        }
    }
    __syncthreads();

    // ================= coord mlp L1: u = silu(M @ cW1 + cb1) [64x64] =========
    float c3[4][4];
    #pragma unroll
    for (int i = 0; i < 4; i++)
        #pragma unroll
        for (int j = 0; j < 4; j++) c3[i][j] = 0.0f;

    for (int kt = 0; kt < 128; kt += 32) {
        #pragma unroll
        for (int l = 0; l < 8; l++) {
            int idx = tid + l * 256;
            int k = idx >> 6, cc = idx & 63;
            Bs[k * 136 + cc] = f2tf(cW1[(size_t)(kt + k) * 64 + cc]);
        }
        __syncthreads();
        #pragma unroll
        for (int ks = 0; ks < 4; ks++) {
            int k0 = ks * 8;
            int kg = kt + k0;
            unsigned a0 = Ms[(wm * 16 + g) * 132 + kg + tig];
            unsigned a1 = Ms[(wm * 16 + g + 8) * 132 + kg + tig];
            unsigned a2 = Ms[(wm * 16 + g) * 132 + kg + tig + 4];
            unsigned a3 = Ms[(wm * 16 + g + 8) * 132 + kg + tig + 4];
            #pragma unroll
            for (int nt = 0; nt < 4; nt++) {
                int ncol = wn * 32 + nt * 8 + g;
                unsigned b0 = Bs[(k0 + tig) * 136 + ncol];
                unsigned b1 = Bs[(k0 + tig + 4) * 136 + ncol];
                mma_tf32(c3[nt], a0, a1, a2, a3, b0, b1);
            }
        }
        __syncthreads();
    }
    // u -> Hs (fp32 bits, reuse)
    #pragma unroll
    for (int nt = 0; nt < 4; nt++) {
        int col = wn * 32 + nt * 8 + 2 * tig;
        int r = wm * 16 + g;
        float b0v = cb1[col], b1v = cb1[col + 1];
        Hs[r * 132 + col]           = __float_as_uint(silu_f(c3[nt][0] + b0v));
        Hs[r * 132 + col + 1]       = __float_as_uint(silu_f(c3[nt][1] + b1v));
        Hs[(r + 8) * 132 + col]     = __float_as_uint(silu_f(c3[nt][2] + b0v));
        Hs[(r + 8) * 132 + col + 1] = __float_as_uint(silu_f(c3[nt][3] + b1v));
    }
    __syncthreads();

    // ================= w = u @ cW2 + cb2 ; coord scatter ==========
    if (tid < 64) {
        int r = tid;
        float w = cb2[0];
        #pragma unroll
        for (int j = 0; j < 64; j++)
            w += __uint_as_float(Hs[r * 132 + j]) * cW2[j];
        if (e0 + r < E) {
            int s = sidx[r], d = didx[r];
            float dx = coords[(size_t)s * 3 + 0] - coords[(size_t)d * 3 + 0];
            float dy = coords[(size_t)s * 3 + 1] - coords[(size_t)d * 3 + 1];
            float dz = coords[(size_t)s * 3 + 2] - coords[(size_t)d * 3 + 2];
            float nrm = sqrtf(dx * dx + dy * dy + dz * dz) + 1e-8f;
            float scl = w / nrm;
            atomicAdd(&g_cacc[(size_t)d * 3 + 0], dx * scl);
            atomicAdd(&g_cacc[(size_t)d * 3 + 1], dy * scl);
            atomicAdd(&g_cacc[(size_t)d * 3 + 2], dz * scl);
        }
    }
}

// ---------------------------------------------------------------------------
// Node kernel: 64-node tile, tf32 tensor-core GEMMs.
//   in  = [x | aggr] (256) -> h = silu(in@nW1+nb1) (128) -> out = x + h@nW2+nb2
//   out_coords = coords + g_cacc
// ---------------------------------------------------------------------------
__global__ __launch_bounds__(256, 2)
void node_kernel(const float* __restrict__ node_feat,
                 const float* __restrict__ coords,
                 const float* __restrict__ nW1, const float* __restrict__ nb1,
                 const float* __restrict__ nW2, const float* __restrict__ nb2,
                 float* __restrict__ out_nodes,
                 float* __restrict__ out_coords,
                 int N)
{
    extern __shared__ unsigned smu[];
    unsigned* As = smu;              // 64 x 36
    unsigned* Bs = As + 64 * 36;     // 32 x 136
    unsigned* Hs = Bs + 32 * 136;    // 64 x 132

    const int tid  = threadIdx.x;
    const int n0   = blockIdx.x * 64;
    const int lane = tid & 31;
    const int wid  = tid >> 5;
    const int g    = lane >> 2;
    const int tig  = lane & 3;
    const int wm   = wid & 3;
    const int wn   = wid >> 2;

    float c[8][4];
    #pragma unroll
    for (int i = 0; i < 8; i++)
        #pragma unroll
        for (int j = 0; j < 4; j++) c[i][j] = 0.0f;

    // layer 1: [64,256] @ [256,128]
    for (int kt = 0; kt < 256; kt += 32) {
        #pragma unroll
        for (int l = 0; l < 8; l++) {
            int idx = tid + l * 256;
            int e = idx >> 5, k = idx & 31;
            int n = n0 + e; if (n >= N) n = N - 1;
            int gg = kt + k;
            float v = (gg < 128) ? node_feat[(size_t)n * 128 + gg]
                                 : g_aggr[(size_t)n * 128 + (gg - 128)];
            As[e * 36 + k] = f2tf(v);
        }
        #pragma unroll
        for (int l = 0; l < 16; l++) {
            int idx = tid + l * 256;
            int k = idx >> 7, cc = idx & 127;
            Bs[k * 136 + cc] = f2tf(nW1[(size_t)(kt + k) * 128 + cc]);
        }
        __syncthreads();
        #pragma unroll
        for (int ks = 0; ks < 4; ks++) {
            int k0 = ks * 8;
            unsigned a0 = As[(wm * 16 + g) * 36 + k0 + tig];
            unsigned a1 = As[(wm * 16 + g + 8) * 36 + k0 + tig];
            unsigned a2 = As[(wm * 16 + g) * 36 + k0 + tig + 4];
            unsigned a3 = As[(wm * 16 + g + 8) * 36 + k0 + tig + 4];
            #pragma unroll
            for (int nt = 0; nt < 8; nt++) {
                int ncol = wn * 64 + nt * 8 + g;
                unsigned b0 = Bs[(k0 + tig) * 136 + ncol];
                unsigned b1 = Bs[(k0 + tig + 4) * 136 + ncol];
                mma_tf32(c[nt], a0, a1, a2, a3, b0, b1);
            }
        }
        __syncthreads();
    }
    #pragma unroll
    for (int nt = 0; nt < 8; nt++) {
        int col = wn * 64 + nt * 8 + 2 * tig;
        int r = wm * 16 + g;
        float b0v = nb1[col], b1v = nb1[col + 1];
        Hs[r * 132 + col]           = f2tf(silu_f(c[nt][0] + b0v));
        Hs[r * 132 + col + 1]       = f2tf(silu_f(c[nt][1] + b1v));
        Hs[(r + 8) * 132 + col]     = f2tf(silu_f(c[nt][2] + b0v));
        Hs[(r + 8) * 132 + col + 1] = f2tf(silu_f(c[nt][3] + b1v));
    }
    __syncthreads();

    // layer 2: [64,128] @ [128,128]
    #pragma unroll
    for (int i = 0; i < 8; i++)
        #pragma unroll
        for (int j = 0; j < 4; j++) c[i][j] = 0.0f;

    for (int kt = 0; kt < 128; kt += 32) {
        #pragma unroll
        for (int l = 0; l < 16; l++) {
            int idx = tid + l * 256;
            int k = idx >> 7, cc = idx & 127;
            Bs[k * 136 + cc] = f2tf(nW2[(size_t)(kt + k) * 128 + cc]);
        }
        __syncthreads();
        #pragma unroll
        for (int ks = 0; ks < 4; ks++) {
            int k0 = ks * 8;
            int kg = kt + k0;
            unsigned a0 = Hs[(wm * 16 + g) * 132 + kg + tig];
            unsigned a1 = Hs[(wm * 16 + g + 8) * 132 + kg + tig];
            unsigned a2 = Hs[(wm * 16 + g) * 132 + kg + tig + 4];
            unsigned a3 = Hs[(wm * 16 + g + 8) * 132 + kg + tig + 4];
            #pragma unroll
            for (int nt = 0; nt < 8; nt++) {
                int ncol = wn * 64 + nt * 8 + g;
                unsigned b0 = Bs[(k0 + tig) * 136 + ncol];
                unsigned b1 = Bs[(k0 + tig + 4) * 136 + ncol];
                mma_tf32(c[nt], a0, a1, a2, a3, b0, b1);
            }
        }
        __syncthreads();
    }
    // residual write
    #pragma unroll
    for (int nt = 0; nt < 8; nt++) {
        int col = wn * 64 + nt * 8 + 2 * tig;
        int r = wm * 16 + g;
        int n = n0 + r;
        if (n < N) {
            out_nodes[(size_t)n * 128 + col] =
                node_feat[(size_t)n * 128 + col] + c[nt][0] + nb2[col];
            out_nodes[(size_t)n * 128 + col + 1] =
                node_feat[(size_t)n * 128 + col + 1] + c[nt][1] + nb2[col + 1];
        }
        n = n0 + r + 8;
        if (n < N) {
            out_nodes[(size_t)n * 128 + col] =
                node_feat[(size_t)n * 128 + col] + c[nt][2] + nb2[col];
            out_nodes[(size_t)n * 128 + col + 1] =
                node_feat[(size_t)n * 128 + col + 1] + c[nt][3] + nb2[col + 1];
        }
    }
    // coords
    if (tid < 192) {
        int e = tid / 3, d = tid % 3;
        int n = n0 + e;
        if (n < N)
            out_coords[(size_t)n * 3 + d] =
                coords[(size_t)n * 3 + d] + g_cacc[(size_t)n * 3 + d];
    }
}

// ---------------------------------------------------------------------------
extern "C" void kernel_launch(void* const* d_in, const int* in_sizes, int n_in,
                              void* d_out, int out_size)
{
    const float* node_feat = (const float*)d_in[0];
    const int*   eidx      = (const int*)  d_in[1];
    const float* edge_attr = (const float*)d_in[2];
    const float* coords    = (const float*)d_in[3];
    const float* eW1 = (const float*)d_in[4];
    const float* eb1 = (const float*)d_in[5];
    const float* eW2 = (const float*)d_in[6];
    const float* eb2 = (const float*)d_in[7];
    const float* nW1 = (const float*)d_in[8];
    const float* nb1 = (const float*)d_in[9];
    const float* nW2 = (const float*)d_in[10];
    const float* nb2 = (const float*)d_in[11];
    const float* cW1 = (const float*)d_in[12];
    const float* cb1 = (const float*)d_in[13];
    const float* cW2 = (const float*)d_in[14];
    const float* cb2 = (const float*)d_in[15];

    const int N = in_sizes[0] / NODE_DIM;
    const int E = in_sizes[1] / 2;
    const int* esrc = eidx;
    const int* edst = eidx + E;

    float* out_nodes  = (float*)d_out;
    float* out_coords = out_nodes + (size_t)N * NODE_DIM;

    constexpr int EDGE_SMEM = (64 * 36 + 32 * 136 + 2 * 64 * 132 + 128) * 4; // 94,720 B
    constexpr int NODE_SMEM = (64 * 36 + 32 * 136 + 64 * 132) * 4;           // 60,416 B
    cudaFuncSetAttribute(edge_kernel, cudaFuncAttributeMaxDynamicSharedMemorySize, EDGE_SMEM);
    cudaFuncSetAttribute(node_kernel, cudaFuncAttributeMaxDynamicSharedMemorySize, NODE_SMEM);

    int zero_elems = N * HID;
    zero_kernel<<<(zero_elems + 255) / 256, 256>>>(N * HID, N * 3);

    edge_kernel<<<(E + 63) / 64, 256, EDGE_SMEM>>>(
        node_feat, esrc, edst, edge_attr, coords,
        eW1, eb1, eW2, eb2, cW1, cb1, cW2, cb2, E);

    node_kernel<<<(N + 63) / 64, 256, NODE_SMEM>>>(
        node_feat, coords, nW1, nb1, nW2, nb2, out_nodes, out_coords, N);
}

// round 9
// speedup vs baseline: 3.1920x; 1.9023x over previous
#include <cuda_runtime.h>
#include <cuda_fp16.h>
#include <math.h>

// Problem constants (fixed by the dataset)
#define MAXN 20000
#define NODE_DIM 128
#define EDGE_DIM 64
#define HID 128

// Weight offsets in half scratch
#define OFF_EW1 0            // 320*128
#define OFF_EW2 40960        // 128*128
#define OFF_CW1 57344        // 128*64
#define OFF_NW1 65536        // 256*128
#define OFF_NW2 98304        // 128*128
#define W_TOTAL 114688

// Scratch (device globals: no allocation allowed)
__device__ float  g_aggr[(size_t)MAXN * HID];   // segment-summed messages (fp32)
__device__ float  g_cacc[(size_t)MAXN * 3];     // coord update accumulator
__device__ __half g_nf_h[(size_t)MAXN * NODE_DIM]; // node_feat in half
__device__ __half g_w_h[W_TOTAL];               // all GEMM weights in half

__device__ __forceinline__ float silu_f(float x) {
    return x / (1.0f + __expf(-x));
}

__device__ __forceinline__ unsigned ssa(const void* p) {
    return (unsigned)__cvta_generic_to_shared(p);
}

__device__ __forceinline__ void ldsm_x4(unsigned addr, unsigned& r0, unsigned& r1,
                                        unsigned& r2, unsigned& r3) {
    asm volatile("ldmatrix.sync.aligned.m8n8.x4.shared.b16 {%0,%1,%2,%3}, [%4];"
                 : "=r"(r0), "=r"(r1), "=r"(r2), "=r"(r3) : "r"(addr));
}
__device__ __forceinline__ void ldsm_x4_t(unsigned addr, unsigned& r0, unsigned& r1,
                                          unsigned& r2, unsigned& r3) {
    asm volatile("ldmatrix.sync.aligned.m8n8.x4.trans.shared.b16 {%0,%1,%2,%3}, [%4];"
                 : "=r"(r0), "=r"(r1), "=r"(r2), "=r"(r3) : "r"(addr));
}
__device__ __forceinline__ void mma_f16(float* c, unsigned a0, unsigned a1,
                                        unsigned a2, unsigned a3,
                                        unsigned b0, unsigned b1) {
    asm volatile("mma.sync.aligned.m16n8k16.row.col.f32.f16.f16.f32 "
                 "{%0,%1,%2,%3}, {%4,%5,%6,%7}, {%8,%9}, {%0,%1,%2,%3};"
                 : "+f"(c[0]), "+f"(c[1]), "+f"(c[2]), "+f"(c[3])
                 : "r"(a0), "r"(a1), "r"(a2), "r"(a3), "r"(b0), "r"(b1));
}

// ---------------------------------------------------------------------------
// Prep: zero scratch, convert node_feat + all weights to half
// ---------------------------------------------------------------------------
__global__ void prep_kernel(const float* __restrict__ node_feat,
                            const float* __restrict__ eW1,
                            const float* __restrict__ eW2,
                            const float* __restrict__ cW1,
                            const float* __restrict__ nW1,
                            const float* __restrict__ nW2,
                            int N)
{
    int i = blockIdx.x * blockDim.x + threadIdx.x;
    int nf = N * NODE_DIM;
    if (i < nf) {
        g_aggr[i] = 0.0f;
        g_nf_h[i] = __float2half_rn(node_feat[i]);
    }
    if (i < N * 3) g_cacc[i] = 0.0f;
    if (i < W_TOTAL) {
        float v;
        if      (i < OFF_EW2) v = eW1[i - OFF_EW1];
        else if (i < OFF_CW1) v = eW2[i - OFF_EW2];
        else if (i < OFF_NW1) v = cW1[i - OFF_CW1];
        else if (i < OFF_NW2) v = nW1[i - OFF_NW1];
        else                  v = nW2[i - OFF_NW2];
        g_w_h[i] = __float2half_rn(v);
    }
}

// ---------------------------------------------------------------------------
// Shared layout strides (in halves). 72 and 136 are both ≡ 8 (mod 64) halves
// => 4 (mod 32) words => ldmatrix phases hit all 32 banks exactly once.
// ---------------------------------------------------------------------------
#define SA 72    // A tile stride (64-k tile)
#define SB 136   // B tile stride (128-n) and H/M stride (128-k rows)

// smem (halves):
//  As: 128 x SA   (18432 B)
//  Bs: 64  x SB   (17408 B)
//  Hs: 128 x SB   (34816 B)
//  Ms: 128 x SB   (34816 B)  [edge kernel only]
//  idx: 2 x 128 int

// ---------------------------------------------------------------------------
// Edge kernel: 128-edge tile, fp16 MMA, fp32 accum.
// ---------------------------------------------------------------------------
__global__ __launch_bounds__(256, 2)
void edge_kernel(const int*   __restrict__ esrc,
                 const int*   __restrict__ edst,
                 const float* __restrict__ edge_attr,
                 const float* __restrict__ coords,
                 const float* __restrict__ eb1,
                 const float* __restrict__ eb2,
                 const float* __restrict__ cb1,
                 const float* __restrict__ cW2,
                 const float* __restrict__ cb2,
                 int E)
{
    extern __shared__ __half smh[];
    __half* As = smh;                 // 128 x 72
    __half* Bs = As + 128 * SA;       // 64 x 136
    __half* Hs = Bs + 64 * SB;        // 128 x 136
    __half* Ms = Hs + 128 * SB;       // 128 x 136
    int* sidx = (int*)(Ms + 128 * SB);
    int* didx = sidx + 128;

    const int tid  = threadIdx.x;
    const int e0   = blockIdx.x * 128;
    const int lane = tid & 31;
    const int wid  = tid >> 5;
    const int g    = lane >> 2;
    const int tig  = lane & 3;
    const int wm   = wid & 3;          // 4 warp-rows (32 each)
    const int wn   = wid >> 2;         // 2 warp-cols (64 each)
    const int RW   = wm * 32;

    const unsigned As_b = ssa(As), Bs_b = ssa(Bs), Hs_b = ssa(Hs), Ms_b = ssa(Ms);
    const int a_row  = lane & 15;
    const int a_koff = (lane >> 4) * 8;

    if (tid < 128) {
        int e = e0 + tid; if (e >= E) e = E - 1;
        sidx[tid] = esrc[e];
        didx[tid] = edst[e];
    }
    __syncthreads();

    float acc[2][8][4];
    #pragma unroll
    for (int m = 0; m < 2; m++)
        #pragma unroll
        for (int n = 0; n < 8; n++)
            #pragma unroll
            for (int j = 0; j < 4; j++) acc[m][n][j] = 0.0f;

    // ===================== layer 1: [128,320] @ [320,128] ====================
    for (int t = 0; t < 5; t++) {
        // ---- gather A tile: 128 edges x 64 k (half) ----
        if (t < 4) {
            const int* idxp = (t < 2) ? sidx : didx;
            int cb = (t & 1) * 64;
            #pragma unroll
            for (int q = 0; q < 4; q++) {
                int i = tid + q * 256;
                int e = i >> 3, v = i & 7;
                const uint4* src = (const uint4*)&g_nf_h[(size_t)idxp[e] * 128 + cb + v * 8];
                *(uint4*)&As[e * SA + v * 8] = *src;
            }
        } else {
            #pragma unroll
            for (int q = 0; q < 8; q++) {
                int i = tid + q * 256;
                int e = i >> 4, v = i & 15;
                int ee = e0 + e; if (ee >= E) ee = E - 1;
                float4 f = *(const float4*)&edge_attr[(size_t)ee * 64 + v * 4];
                __half2 h0 = __floats2half2_rn(f.x, f.y);
                __half2 h1 = __floats2half2_rn(f.z, f.w);
                *(__half2*)&As[e * SA + v * 4]     = h0;
                *(__half2*)&As[e * SA + v * 4 + 2] = h1;
            }
        }
        // ---- load B tile: eW1 rows [64t, 64t+64) x 128 ----
        #pragma unroll
        for (int q = 0; q < 4; q++) {
            int i = tid + q * 256;
            int k = i >> 4, v = i & 15;
            *(uint4*)&Bs[k * SB + v * 8] =
                *(const uint4*)&g_w_h[OFF_EW1 + (size_t)(t * 64 + k) * 128 + v * 8];
        }
        __syncthreads();
        #pragma unroll
        for (int c0 = 0; c0 < 64; c0 += 16) {
            unsigned ua[2][4], ub[4][4];
            #pragma unroll
            for (int m = 0; m < 2; m++)
                ldsm_x4(As_b + ((RW + m * 16 + a_row) * SA + c0 + a_koff) * 2,
                        ua[m][0], ua[m][1], ua[m][2], ua[m][3]);
            #pragma unroll
            for (int p = 0; p < 4; p++)
                ldsm_x4_t(Bs_b + ((c0 + a_row) * SB + wn * 64 + p * 16 + a_koff) * 2,
                          ub[p][0], ub[p][1], ub[p][2], ub[p][3]);
            #pragma unroll
            for (int m = 0; m < 2; m++)
                #pragma unroll
                for (int p = 0; p < 4; p++) {
                    mma_f16(acc[m][2 * p],     ua[m][0], ua[m][1], ua[m][2], ua[m][3], ub[p][0], ub[p][1]);
                    mma_f16(acc[m][2 * p + 1], ua[m][0], ua[m][1], ua[m][2], ua[m][3], ub[p][2], ub[p][3]);
                }
        }
        __syncthreads();
    }
    // h1 = silu(acc + eb1) -> Hs
    #pragma unroll
    for (int m = 0; m < 2; m++)
        #pragma unroll
        for (int n = 0; n < 8; n++) {
            int r = RW + m * 16 + g;
            int c = wn * 64 + n * 8 + 2 * tig;
            float b0 = eb1[c], b1 = eb1[c + 1];
            *(__half2*)&Hs[r * SB + c] =
                __floats2half2_rn(silu_f(acc[m][n][0] + b0), silu_f(acc[m][n][1] + b1));
            *(__half2*)&Hs[(r + 8) * SB + c] =
                __floats2half2_rn(silu_f(acc[m][n][2] + b0), silu_f(acc[m][n][3] + b1));
        }
    __syncthreads();

    // ===================== layer 2: [128,128] @ [128,128] ====================
    #pragma unroll
    for (int m = 0; m < 2; m++)
        #pragma unroll
        for (int n = 0; n < 8; n++)
            #pragma unroll
            for (int j = 0; j < 4; j++) acc[m][n][j] = 0.0f;

    for (int t = 0; t < 2; t++) {
        #pragma unroll
        for (int q = 0; q < 4; q++) {
            int i = tid + q * 256;
            int k = i >> 4, v = i & 15;
            *(uint4*)&Bs[k * SB + v * 8] =
                *(const uint4*)&g_w_h[OFF_EW2 + (size_t)(t * 64 + k) * 128 + v * 8];
        }
        __syncthreads();
        #pragma unroll
        for (int c0 = 0; c0 < 64; c0 += 16) {
            unsigned ua[2][4], ub[4][4];
            #pragma unroll
            for (int m = 0; m < 2; m++)
                ldsm_x4(Hs_b + ((RW + m * 16 + a_row) * SB + t * 64 + c0 + a_koff) * 2,
                        ua[m][0], ua[m][1], ua[m][2], ua[m][3]);
            #pragma unroll
            for (int p = 0; p < 4; p++)
                ldsm_x4_t(Bs_b + ((c0 + a_row) * SB + wn * 64 + p * 16 + a_koff) * 2,
                          ub[p][0], ub[p][1], ub[p][2], ub[p][3]);
            #pragma unroll
            for (int m = 0; m < 2; m++)
                #pragma unroll
                for (int p = 0; p < 4; p++) {
                    mma_f16(acc[m][2 * p],     ua[m][0], ua[m][1], ua[m][2], ua[m][3], ub[p][0], ub[p][1]);
                    mma_f16(acc[m][2 * p + 1], ua[m][0], ua[m][1], ua[m][2], ua[m][3], ub[p][2], ub[p][3]);
                }
        }
        __syncthreads();
    }
    // m = silu(acc + eb2): fp32 atomics to g_aggr + half store to Ms
    #pragma unroll
    for (int m = 0; m < 2; m++)
        #pragma unroll
        for (int n = 0; n < 8; n++) {
            int r = RW + m * 16 + g;
            int c = wn * 64 + n * 8 + 2 * tig;
            float b0 = eb2[c], b1 = eb2[c + 1];
            float m00 = silu_f(acc[m][n][0] + b0), m01 = silu_f(acc[m][n][1] + b1);
            float m10 = silu_f(acc[m][n][2] + b0), m11 = silu_f(acc[m][n][3] + b1);
            *(__half2*)&Ms[r * SB + c]       = __floats2half2_rn(m00, m01);
            *(__half2*)&Ms[(r + 8) * SB + c] = __floats2half2_rn(m10, m11);
            if (e0 + r < E) {
                int d = didx[r];
                atomicAdd(&g_aggr[(size_t)d * 128 + c],     m00);
                atomicAdd(&g_aggr[(size_t)d * 128 + c + 1], m01);
            }
            if (e0 + r + 8 < E) {
                int d = didx[r + 8];
                atomicAdd(&g_aggr[(size_t)d * 128 + c],     m10);
                atomicAdd(&g_aggr[(size_t)d * 128 + c + 1], m11);
            }
        }
    __syncthreads();

    // ============== coord mlp L1: u = silu(M @ cW1 + cb1) [128x64] ===========
    float c3[2][4][4];
    #pragma unroll
    for (int m = 0; m < 2; m++)
        #pragma unroll
        for (int n = 0; n < 4; n++)
            #pragma unroll
            for (int j = 0; j < 4; j++) c3[m][n][j] = 0.0f;

    for (int t = 0; t < 2; t++) {
        #pragma unroll
        for (int q = 0; q < 2; q++) {
            int i = tid + q * 256;
            int k = i >> 3, v = i & 7;
            *(uint4*)&Bs[k * SB + v * 8] =
                *(const uint4*)&g_w_h[OFF_CW1 + (size_t)(t * 64 + k) * 64 + v * 8];
        }
        __syncthreads();
        #pragma unroll
        for (int c0 = 0; c0 < 64; c0 += 16) {
            unsigned ua[2][4], ub[2][4];
            #pragma unroll
            for (int m = 0; m < 2; m++)
                ldsm_x4(Ms_b + ((RW + m * 16 + a_row) * SB + t * 64 + c0 + a_koff) * 2,
                        ua[m][0], ua[m][1], ua[m][2], ua[m][3]);
            #pragma unroll
            for (int p = 0; p < 2; p++)
                ldsm_x4_t(Bs_b + ((c0 + a_row) * SB + wn * 32 + p * 16 + a_koff) * 2,
                          ub[p][0], ub[p][1], ub[p][2], ub[p][3]);
            #pragma unroll
            for (int m = 0; m < 2; m++)
                #pragma unroll
                for (int p = 0; p < 2; p++) {
                    mma_f16(c3[m][2 * p],     ua[m][0], ua[m][1], ua[m][2], ua[m][3], ub[p][0], ub[p][1]);
                    mma_f16(c3[m][2 * p + 1], ua[m][0], ua[m][1], ua[m][2], ua[m][3], ub[p][2], ub[p][3]);
                }
        }
        __syncthreads();
    }
    // u -> Hs cols [0,64)
    #pragma unroll
    for (int m = 0; m < 2; m++)
        #pragma unroll
        for (int n = 0; n < 4; n++) {
            int r = RW + m * 16 + g;
            int c = wn * 32 + n * 8 + 2 * tig;
            float b0 = cb1[c], b1 = cb1[c + 1];
            *(__half2*)&Hs[r * SB + c] =
                __floats2half2_rn(silu_f(c3[m][n][0] + b0), silu_f(c3[m][n][1] + b1));
            *(__half2*)&Hs[(r + 8) * SB + c] =
                __floats2half2_rn(silu_f(c3[m][n][2] + b0), silu_f(c3[m][n][3] + b1));
        }
    __syncthreads();

    // ============== w = u @ cW2 + cb2 ; coord scatter ==============
    if (tid < 128) {
        int r = tid;
        float w = cb2[0];
        #pragma unroll
        for (int j = 0; j < 64; j += 2) {
            __half2 h = *(__half2*)&Hs[r * SB + j];
            float2 f = __half22float2(h);
            w += f.x * cW2[j] + f.y * cW2[j + 1];
        }
        if (e0 + r < E) {
            int s = sidx[r], d = didx[r];
            float dx = coords[(size_t)s * 3 + 0] - coords[(size_t)d * 3 + 0];
            float dy = coords[(size_t)s * 3 + 1] - coords[(size_t)d * 3 + 1];
            float dz = coords[(size_t)s * 3 + 2] - coords[(size_t)d * 3 + 2];
            float nrm = sqrtf(dx * dx + dy * dy + dz * dz) + 1e-8f;
            float scl = w / nrm;
            atomicAdd(&g_cacc[(size_t)d * 3 + 0], dx * scl);
            atomicAdd(&g_cacc[(size_t)d * 3 + 1], dy * scl);
            atomicAdd(&g_cacc[(size_t)d * 3 + 2], dz * scl);
        }
    }
}

// ---------------------------------------------------------------------------
// Node kernel: 128-node tile, fp16 MMA.
// ---------------------------------------------------------------------------
__global__ __launch_bounds__(256, 2)
void node_kernel(const float* __restrict__ node_feat,
                 const float* __restrict__ coords,
                 const float* __restrict__ nb1,
                 const float* __restrict__ nb2,
                 float* __restrict__ out_nodes,
                 float* __restrict__ out_coords,
                 int N)
{
    extern __shared__ __half smh[];
    __half* As = smh;                 // 128 x 72
    __half* Bs = As + 128 * SA;       // 64 x 136
    __half* Hs = Bs + 64 * SB;        // 128 x 136

    const int tid  = threadIdx.x;
    const int n0   = blockIdx.x * 128;
    const int lane = tid & 31;
    const int wid  = tid >> 5;
    const int g    = lane >> 2;
    const int tig  = lane & 3;
    const int wm   = wid & 3;
    const int wn   = wid >> 2;
    const int RW   = wm * 32;

    const unsigned As_b = ssa(As), Bs_b = ssa(Bs), Hs_b = ssa(Hs);
    const int a_row  = lane & 15;
    const int a_koff = (lane >> 4) * 8;

    float acc[2][8][4];
    #pragma unroll
    for (int m = 0; m < 2; m++)
        #pragma unroll
        for (int n = 0; n < 8; n++)
            #pragma unroll
            for (int j = 0; j < 4; j++) acc[m][n][j] = 0.0f;

    // layer 1: [128,256] @ [256,128]
    for (int t = 0; t < 4; t++) {
        if (t < 2) {
            int cb = t * 64;
            #pragma unroll
            for (int q = 0; q < 4; q++) {
                int i = tid + q * 256;
                int e = i >> 3, v = i & 7;
                int n = n0 + e; if (n >= N) n = N - 1;
                *(uint4*)&As[e * SA + v * 8] =
                    *(const uint4*)&g_nf_h[(size_t)n * 128 + cb + v * 8];
            }
        } else {
            int cb = (t - 2) * 64;
            #pragma unroll
            for (int q = 0; q < 8; q++) {
                int i = tid + q * 256;
                int e = i >> 4, v = i & 15;
                int n = n0 + e; if (n >= N) n = N - 1;
                float4 f = *(const float4*)&g_aggr[(size_t)n * 128 + cb + v * 4];
                *(__half2*)&As[e * SA + v * 4]     = __floats2half2_rn(f.x, f.y);
                *(__half2*)&As[e * SA + v * 4 + 2] = __floats2half2_rn(f.z, f.w);
            }
        }
        #pragma unroll
        for (int q = 0; q < 4; q++) {
            int i = tid + q * 256;
            int k = i >> 4, v = i & 15;
            *(uint4*)&Bs[k * SB + v * 8] =
                *(const uint4*)&g_w_h[OFF_NW1 + (size_t)(t * 64 + k) * 128 + v * 8];
        }
        __syncthreads();
        #pragma unroll
        for (int c0 = 0; c0 < 64; c0 += 16) {
            unsigned ua[2][4], ub[4][4];
            #pragma unroll
            for (int m = 0; m < 2; m++)
                ldsm_x4(As_b + ((RW + m * 16 + a_row) * SA + c0 + a_koff) * 2,
                        ua[m][0], ua[m][1], ua[m][2], ua[m][3]);
            #pragma unroll
            for (int p = 0; p < 4; p++)
                ldsm_x4_t(Bs_b + ((c0 + a_row) * SB + wn * 64 + p * 16 + a_koff) * 2,
                          ub[p][0], ub[p][1], ub[p][2], ub[p][3]);
            #pragma unroll
            for (int m = 0; m < 2; m++)
                #pragma unroll
                for (int p = 0; p < 4; p++) {
                    mma_f16(acc[m][2 * p],     ua[m][0], ua[m][1], ua[m][2], ua[m][3], ub[p][0], ub[p][1]);
                    mma_f16(acc[m][2 * p + 1], ua[m][0], ua[m][1], ua[m][2], ua[m][3], ub[p][2], ub[p][3]);
                }
        }
        __syncthreads();
    }
    #pragma unroll
    for (int m = 0; m < 2; m++)
        #pragma unroll
        for (int n = 0; n < 8; n++) {
            int r = RW + m * 16 + g;
            int c = wn * 64 + n * 8 + 2 * tig;
            float b0 = nb1[c], b1 = nb1[c + 1];
            *(__half2*)&Hs[r * SB + c] =
                __floats2half2_rn(silu_f(acc[m][n][0] + b0), silu_f(acc[m][n][1] + b1));
            *(__half2*)&Hs[(r + 8) * SB + c] =
                __floats2half2_rn(silu_f(acc[m][n][2] + b0), silu_f(acc[m][n][3] + b1));
        }
    __syncthreads();

    // layer 2: [128,128] @ [128,128]
    #pragma unroll
    for (int m = 0; m < 2; m++)
        #pragma unroll
        for (int n = 0; n < 8; n++)
            #pragma unroll
            for (int j = 0; j < 4; j++) acc[m][n][j] = 0.0f;

    for (int t = 0; t < 2; t++) {
        #pragma unroll
        for (int q = 0; q < 4; q++) {
            int i = tid + q * 256;
            int k = i >> 4, v = i & 15;
            *(uint4*)&Bs[k * SB + v * 8] =
                *(const uint4*)&g_w_h[OFF_NW2 + (size_t)(t * 64 + k) * 128 + v * 8];
        }
        __syncthreads();
        #pragma unroll
        for (int c0 = 0; c0 < 64; c0 += 16) {
            unsigned ua[2][4], ub[4][4];
            #pragma unroll
            for (int m = 0; m < 2; m++)
                ldsm_x4(Hs_b + ((RW + m * 16 + a_row) * SB + t * 64 + c0 + a_koff) * 2,
                        ua[m][0], ua[m][1], ua[m][2], ua[m][3]);
            #pragma unroll
            for (int p = 0; p < 4; p++)
                ldsm_x4_t(Bs_b + ((c0 + a_row) * SB + wn * 64 + p * 16 + a_koff) * 2,
                          ub[p][0], ub[p][1], ub[p][2], ub[p][3]);
            #pragma unroll
            for (int m = 0; m < 2; m++)
                #pragma unroll
                for (int p = 0; p < 4; p++) {
                    mma_f16(acc[m][2 * p],     ua[m][0], ua[m][1], ua[m][2], ua[m][3], ub[p][0], ub[p][1]);
                    mma_f16(acc[m][2 * p + 1], ua[m][0], ua[m][1], ua[m][2], ua[m][3], ub[p][2], ub[p][3]);
                }
        }
        __syncthreads();
    }
    // residual write
    #pragma unroll
    for (int m = 0; m < 2; m++)
        #pragma unroll
        for (int n = 0; n < 8; n++) {
            int r = RW + m * 16 + g;
            int c = wn * 64 + n * 8 + 2 * tig;
            int nn = n0 + r;
            if (nn < N) {
                out_nodes[(size_t)nn * 128 + c] =
                    node_feat[(size_t)nn * 128 + c] + acc[m][n][0] + nb2[c];
                out_nodes[(size_t)nn * 128 + c + 1] =
                    node_feat[(size_t)nn * 128 + c + 1] + acc[m][n][1] + nb2[c + 1];
            }
            nn = n0 + r + 8;
            if (nn < N) {
                out_nodes[(size_t)nn * 128 + c] =
                    node_feat[(size_t)nn * 128 + c] + acc[m][n][2] + nb2[c];
                out_nodes[(size_t)nn * 128 + c + 1] =
                    node_feat[(size_t)nn * 128 + c + 1] + acc[m][n][3] + nb2[c + 1];
            }
        }
    // coords
    for (int i = tid; i < 128 * 3; i += 256) {
        int e = i / 3, d = i % 3;
        int n = n0 + e;
        if (n < N)
            out_coords[(size_t)n * 3 + d] =
                coords[(size_t)n * 3 + d] + g_cacc[(size_t)n * 3 + d];
    }
}

// ---------------------------------------------------------------------------
extern "C" void kernel_launch(void* const* d_in, const int* in_sizes, int n_in,
                              void* d_out, int out_size)
{
    const float* node_feat = (const float*)d_in[0];
    const int*   eidx      = (const int*)  d_in[1];
    const float* edge_attr = (const float*)d_in[2];
    const float* coords    = (const float*)d_in[3];
    const float* eW1 = (const float*)d_in[4];
    const float* eb1 = (const float*)d_in[5];
    const float* eW2 = (const float*)d_in[6];
    const float* eb2 = (const float*)d_in[7];
    const float* nW1 = (const float*)d_in[8];
    const float* nb1 = (const float*)d_in[9];
    const float* nW2 = (const float*)d_in[10];
    const float* nb2 = (const float*)d_in[11];
    const float* cW1 = (const float*)d_in[12];
    const float* cb1 = (const float*)d_in[13];
    const float* cW2 = (const float*)d_in[14];
    const float* cb2 = (const float*)d_in[15];

    const int N = in_sizes[0] / NODE_DIM;
    const int E = in_sizes[1] / 2;
    const int* esrc = eidx;
    const int* edst = eidx + E;

    float* out_nodes  = (float*)d_out;
    float* out_coords = out_nodes + (size_t)N * NODE_DIM;

    constexpr int EDGE_SMEM = (128 * SA + 64 * SB + 2 * 128 * SB) * 2 + 256 * 4; // 106,496 B
    constexpr int NODE_SMEM = (128 * SA + 64 * SB + 128 * SB) * 2;               //  70,656 B
    cudaFuncSetAttribute(edge_kernel, cudaFuncAttributeMaxDynamicSharedMemorySize, EDGE_SMEM);
    cudaFuncSetAttribute(node_kernel, cudaFuncAttributeMaxDynamicSharedMemorySize, NODE_SMEM);

    prep_kernel<<<(N * NODE_DIM + 255) / 256, 256>>>(node_feat, eW1, eW2, cW1, nW1, nW2, N);

    edge_kernel<<<(E + 127) / 128, 256, EDGE_SMEM>>>(
        esrc, edst, edge_attr, coords, eb1, eb2, cb1, cW2, cb2, E);

    node_kernel<<<(N + 127) / 128, 256, NODE_SMEM>>>(
        node_feat, coords, nb1, nb2, out_nodes, out_coords, N);
}

// round 13
// speedup vs baseline: 5.3413x; 1.6734x over previous
#include <cuda_runtime.h>
#include <cuda_fp16.h>
#include <math.h>

// Problem constants (fixed by the dataset)
#define MAXN 20000
#define NODE_DIM 128
#define EDGE_DIM 64
#define HID 128

// Weight offsets in half scratch
#define OFF_EW1 0            // 320*128
#define OFF_EW2 40960        // 128*128
#define OFF_CW1 57344        // 128*64
#define OFF_NW1 65536        // 256*128
#define OFF_NW2 98304        // 128*128
#define W_TOTAL 114688

// Shared strides (halves): all == 8 (mod 64) halves -> conflict-free ldmatrix
#define SA 72
#define SB 136
#define SC 72

// Scratch (device globals: no allocation allowed)
__device__ float  g_aggr[(size_t)MAXN * HID];      // segment-summed messages (fp32)
__device__ float  g_cacc[(size_t)MAXN * 3];        // coord update accumulator
__device__ __half g_nf_h[(size_t)MAXN * NODE_DIM]; // node_feat in half
__device__ __half g_ag_h[(size_t)MAXN * HID];      // aggr in half (post-edge)
__device__ __half g_w_h[W_TOTAL];                  // all GEMM weights in half

__device__ __forceinline__ float silu_f(float x) {
    return x / (1.0f + __expf(-x));
}
__device__ __forceinline__ unsigned ssa(const void* p) {
    return (unsigned)__cvta_generic_to_shared(p);
}
__device__ __forceinline__ unsigned pack2(float x, float y) {
    __half2 h = __floats2half2_rn(x, y);
    return *(unsigned*)&h;
}
__device__ __forceinline__ void cp16(unsigned saddr, const void* g) {
    asm volatile("cp.async.ca.shared.global [%0], [%1], 16;" :: "r"(saddr), "l"(g));
}
__device__ __forceinline__ void cp_commit() {
    asm volatile("cp.async.commit_group;");
}
template <int N>
__device__ __forceinline__ void cp_wait() {
    asm volatile("cp.async.wait_group %0;" :: "n"(N));
}
__device__ __forceinline__ void ldsm_x4(unsigned addr, unsigned& r0, unsigned& r1,
                                        unsigned& r2, unsigned& r3) {
    asm volatile("ldmatrix.sync.aligned.m8n8.x4.shared.b16 {%0,%1,%2,%3}, [%4];"
                 : "=r"(r0), "=r"(r1), "=r"(r2), "=r"(r3) : "r"(addr));
}
__device__ __forceinline__ void ldsm_x4_t(unsigned addr, unsigned& r0, unsigned& r1,
                                          unsigned& r2, unsigned& r3) {
    asm volatile("ldmatrix.sync.aligned.m8n8.x4.trans.shared.b16 {%0,%1,%2,%3}, [%4];"
                 : "=r"(r0), "=r"(r1), "=r"(r2), "=r"(r3) : "r"(addr));
}
__device__ __forceinline__ void mma_f16(float* c, unsigned a0, unsigned a1,
                                        unsigned a2, unsigned a3,
                                        unsigned b0, unsigned b1) {
    asm volatile("mma.sync.aligned.m16n8k16.row.col.f32.f16.f16.f32 "
                 "{%0,%1,%2,%3}, {%4,%5,%6,%7}, {%8,%9}, {%0,%1,%2,%3};"
                 : "+f"(c[0]), "+f"(c[1]), "+f"(c[2]), "+f"(c[3])
                 : "r"(a0), "r"(a1), "r"(a2), "r"(a3), "r"(b0), "r"(b1));
}

// GEMM over one staged k64 tile: A from smem (ldmatrix), warp rows fixed.
// NP = number of 16-col B pairs (NP=8 -> N=128).
template <int NP>
__device__ __forceinline__ void gemm_k64(float (*acc)[4], unsigned a_base, int sa,
                                         unsigned b_base, int sb,
                                         int a_row, int a_koff) {
    #pragma unroll
    for (int ks = 0; ks < 4; ks++) {
        unsigned a0, a1, a2, a3;
        ldsm_x4(a_base + (a_row * sa + ks * 16 + a_koff) * 2, a0, a1, a2, a3);
        #pragma unroll
        for (int p = 0; p < NP; p++) {
            unsigned b0, b1, b2, b3;
            ldsm_x4_t(b_base + ((ks * 16 + a_row) * sb + p * 16 + a_koff) * 2,
                      b0, b1, b2, b3);
            mma_f16(acc[2 * p],     a0, a1, a2, a3, b0, b1);
            mma_f16(acc[2 * p + 1], a0, a1, a2, a3, b2, b3);
        }
    }
}

// GEMM with A in registers (8 k16 fragments), B from two 64-row smem buffers.
template <int NP>
__device__ __forceinline__ void gemm_regA(float (*acc)[4], const unsigned (*af)[4],
                                          unsigned b_buf0, unsigned b_buf1, int sb,
                                          int a_row, int a_koff) {
    #pragma unroll
    for (int j = 0; j < 8; j++) {
        unsigned base = (j < 4) ? b_buf0 : b_buf1;
        int lr = (j & 3) * 16;
        #pragma unroll
        for (int p = 0; p < NP; p++) {
            unsigned b0, b1, b2, b3;
            ldsm_x4_t(base + ((lr + a_row) * sb + p * 16 + a_koff) * 2,
                      b0, b1, b2, b3);
            mma_f16(acc[2 * p],     af[j][0], af[j][1], af[j][2], af[j][3], b0, b1);
            mma_f16(acc[2 * p + 1], af[j][0], af[j][1], af[j][2], af[j][3], b2, b3);
        }
    }
}

// ---------------------------------------------------------------------------
// Prep: zero scratch, convert node_feat + all weights to half
// ---------------------------------------------------------------------------
__global__ void prep_kernel(const float* __restrict__ node_feat,
                            const float* __restrict__ eW1,
                            const float* __restrict__ eW2,
                            const float* __restrict__ cW1,
                            const float* __restrict__ nW1,
                            const float* __restrict__ nW2,
                            int N)
{
    int i = blockIdx.x * blockDim.x + threadIdx.x;
    int nf = N * NODE_DIM;
    if (i < nf) {
        g_aggr[i] = 0.0f;
        g_nf_h[i] = __float2half_rn(node_feat[i]);
    }
    if (i < N * 3) g_cacc[i] = 0.0f;
    if (i < W_TOTAL) {
        float v;
        if      (i < OFF_EW2) v = eW1[i - OFF_EW1];
        else if (i < OFF_CW1) v = eW2[i - OFF_EW2];
        else if (i < OFF_NW1) v = cW1[i - OFF_CW1];
        else if (i < OFF_NW2) v = nW1[i - OFF_NW1];
        else                  v = nW2[i - OFF_NW2];
        g_w_h[i] = __float2half_rn(v);
    }
}

// Convert aggregated messages to half (runs after edge kernel)
__global__ void cvt_aggr_kernel(int n) {
    int i = blockIdx.x * blockDim.x + threadIdx.x;
    if (i < n) g_ag_h[i] = __float2half_rn(g_aggr[i]);
}

// ---------------------------------------------------------------------------
// Edge kernel: 128-edge tile; warp = 16 edges x full width.
// Layers chained in registers; cp.async double-buffered pipeline.
// smem (halves): As[2][128*SA] | Bs[2][64*SB] | W2s[2][64*SB] | idx
// C1s (cW1 tiles, 2 x 64*SC) overlays the As region after layer 1.
// ---------------------------------------------------------------------------
__global__ __launch_bounds__(256, 2)
void edge_kernel(const int*   __restrict__ esrc,
                 const int*   __restrict__ edst,
                 const float* __restrict__ edge_attr,
                 const float* __restrict__ coords,
                 const float* __restrict__ eb1,
                 const float* __restrict__ eb2,
                 const float* __restrict__ cb1,
                 const float* __restrict__ cW2,
                 const float* __restrict__ cb2,
                 int E)
{
    extern __shared__ __half smh[];
    __half* As  = smh;                        // 2 x 9216
    __half* Bs  = smh + 2 * 128 * SA;         // 2 x 8704
    __half* W2s = Bs + 2 * 64 * SB;           // 2 x 8704
    int* sidx = (int*)(W2s + 2 * 64 * SB);    // 128
    int* didx = sidx + 128;                   // 128

    const int tid  = threadIdx.x;
    const int e0   = blockIdx.x * 128;
    const int lane = tid & 31;
    const int wid  = tid >> 5;
    const int g    = lane >> 2;
    const int tig  = lane & 3;
    const int RW   = wid * 16;                // warp's 16 rows

    const unsigned As_b  = ssa(As);
    const unsigned Bs_b  = ssa(Bs);
    const unsigned W2s_b = ssa(W2s);
    const int a_row  = lane & 15;
    const int a_koff = (lane >> 4) * 8;

    if (tid < 128) {
        int e = e0 + tid; if (e >= E) e = E - 1;
        sidx[tid] = esrc[e];
        didx[tid] = edst[e];
    }
    __syncthreads();

    // A tile: 128 rows x 64 halves -> 1024 cp16 (4 per thread)
    #define ISSUE_A_NF(T, BUF) do {                                          \
        const int* idxp = ((T) < 2) ? sidx : didx;                           \
        int cb = ((T) & 1) * 64;                                             \
        unsigned dstb = As_b + (BUF) * 128 * SA * 2;                         \
        _Pragma("unroll")                                                    \
        for (int q = 0; q < 4; q++) {                                        \
            int i = tid + q * 256;                                           \
            int e = i >> 3, v = i & 7;                                       \
            cp16(dstb + (e * SA + v * 8) * 2,                                \
                 &g_nf_h[(size_t)idxp[e] * 128 + cb + v * 8]);               \
        }                                                                    \
    } while (0)

    // B tile: 64 rows x 128 halves -> 1024 cp16 (4 per thread)
    #define ISSUE_B_EW1(T, BUF) do {                                         \
        unsigned dstb = Bs_b + (BUF) * 64 * SB * 2;                          \
        _Pragma("unroll")                                                    \
        for (int q = 0; q < 4; q++) {                                        \
            int i = tid + q * 256;                                           \
            int k = i >> 4, v = i & 15;                                      \
            cp16(dstb + (k * SB + v * 8) * 2,                                \
                 &g_w_h[OFF_EW1 + (size_t)((T) * 64 + k) * 128 + v * 8]);    \
        }                                                                    \
    } while (0)

    // prologue: T0, then eW2 (2 tiles x 64 x 128 halves -> 2048 cp16)
    ISSUE_A_NF(0, 0); ISSUE_B_EW1(0, 0); cp_commit();          // T0
    #pragma unroll
    for (int q = 0; q < 8; q++) {                              // W2 group
        int i = tid + q * 256;
        int jj = i >> 10, i2 = i & 1023;
        int k = i2 >> 4, v = i2 & 15;
        cp16(W2s_b + (jj * 64 * SB + k * SB + v * 8) * 2,
             &g_w_h[OFF_EW2 + (size_t)(jj * 64 + k) * 128 + v * 8]);
    }
    cp_commit();                                               // W2

    float acc[16][4];
    #pragma unroll
    for (int n = 0; n < 16; n++)
        #pragma unroll
        for (int j = 0; j < 4; j++) acc[n][j] = 0.0f;

    const unsigned aw0 = As_b + RW * SA * 2;                   // warp A base buf0
    const unsigned aw1 = As_b + (128 * SA + RW * SA) * 2;      // buf1
    const unsigned bb0 = Bs_b;
    const unsigned bb1 = Bs_b + 64 * SB * 2;

    // ---- t=0 ----
    ISSUE_A_NF(1, 1); ISSUE_B_EW1(1, 1); cp_commit();          // T1
    cp_wait<2>(); __syncthreads();
    gemm_k64<8>(acc, aw0, SA, bb0, SB, a_row, a_koff);
    __syncthreads();
    // ---- t=1 ----
    ISSUE_A_NF(2, 0); ISSUE_B_EW1(2, 0); cp_commit();          // T2
    cp_wait<1>(); __syncthreads();
    gemm_k64<8>(acc, aw1, SA, bb1, SB, a_row, a_koff);
    __syncthreads();
    // ---- t=2 ----
    ISSUE_A_NF(3, 1); ISSUE_B_EW1(3, 1); cp_commit();          // T3
    cp_wait<1>(); __syncthreads();
    gemm_k64<8>(acc, aw0, SA, bb0, SB, a_row, a_koff);
    __syncthreads();
    // ---- t=3: attr tile (plain ld+cvt+sts into A buf0) + eW1 tile4 async ----
    {
        #pragma unroll
        for (int q = 0; q < 8; q++) {
            int i = tid + q * 256;
            int e = i >> 4, v = i & 15;
            int ee = e0 + e; if (ee >= E) ee = E - 1;
            float4 f = *(const float4*)&edge_attr[(size_t)ee * 64 + v * 4];
            *(__half2*)&As[e * SA + v * 4]     = __floats2half2_rn(f.x, f.y);
            *(__half2*)&As[e * SA + v * 4 + 2] = __floats2half2_rn(f.z, f.w);
        }
        ISSUE_B_EW1(4, 0); cp_commit();                        // B4
    }
    cp_wait<1>(); __syncthreads();
    gemm_k64<8>(acc, aw1, SA, bb1, SB, a_row, a_koff);
    __syncthreads();
    // ---- t=4 ----
    cp_wait<0>(); __syncthreads();
    gemm_k64<8>(acc, aw0, SA, bb0, SB, a_row, a_koff);
    __syncthreads();

    // ---- pack h1 = silu(acc + eb1) into layer-2 A fragments (registers) ----
    unsigned ah[8][4];
    #pragma unroll
    for (int j = 0; j < 8; j++) {
        int c0 = 16 * j + 2 * tig;
        int c1 = c0 + 8;
        float b00 = eb1[c0], b01 = eb1[c0 + 1];
        float b10 = eb1[c1], b11 = eb1[c1 + 1];
        ah[j][0] = pack2(silu_f(acc[2*j][0] + b00),   silu_f(acc[2*j][1] + b01));
        ah[j][1] = pack2(silu_f(acc[2*j][2] + b00),   silu_f(acc[2*j][3] + b01));
        ah[j][2] = pack2(silu_f(acc[2*j+1][0] + b10), silu_f(acc[2*j+1][1] + b11));
        ah[j][3] = pack2(silu_f(acc[2*j+1][2] + b10), silu_f(acc[2*j+1][3] + b11));
    }

    // prefetch cW1 into As region (free now): 2 tiles x 64 x 64 halves -> 1024 cp16
    #pragma unroll
    for (int q = 0; q < 4; q++) {
        int i = tid + q * 256;
        int jj = i >> 9, i2 = i & 511;
        int k = i2 >> 3, v = i2 & 7;
        cp16(As_b + (jj * 64 * SC + k * SC + v * 8) * 2,
             &g_w_h[OFF_CW1 + (size_t)(jj * 64 + k) * 64 + v * 8]);
    }
    cp_commit();                                               // C1

    // ---- layer 2: acc2 = h1 @ eW2 (A in regs, B resident in W2s) ----
    float acc2[16][4];
    #pragma unroll
    for (int n = 0; n < 16; n++)
        #pragma unroll
        for (int j = 0; j < 4; j++) acc2[n][j] = 0.0f;
    gemm_regA<8>(acc2, ah, W2s_b, W2s_b + 64 * SB * 2, SB, a_row, a_koff);

    // ---- m = silu(acc2 + eb2): pack to coord-A frags + fp32 atomics ----
    unsigned am[8][4];
    const int r0 = RW + g, r1 = RW + g + 8;
    const bool ok0 = (e0 + r0) < E, ok1 = (e0 + r1) < E;
    const int d0 = didx[r0], d1 = didx[r1];
    #pragma unroll
    for (int j = 0; j < 8; j++) {
        int c0 = 16 * j + 2 * tig;
        int c1 = c0 + 8;
        float b00 = eb2[c0], b01 = eb2[c0 + 1];
        float b10 = eb2[c1], b11 = eb2[c1 + 1];
        float m00 = silu_f(acc2[2*j][0] + b00),   m01 = silu_f(acc2[2*j][1] + b01);
        float m10 = silu_f(acc2[2*j][2] + b00),   m11 = silu_f(acc2[2*j][3] + b01);
        float m20 = silu_f(acc2[2*j+1][0] + b10), m21 = silu_f(acc2[2*j+1][1] + b11);
        float m30 = silu_f(acc2[2*j+1][2] + b10), m31 = silu_f(acc2[2*j+1][3] + b11);
        am[j][0] = pack2(m00, m01);
        am[j][1] = pack2(m10, m11);
        am[j][2] = pack2(m20, m21);
        am[j][3] = pack2(m30, m31);
        if (ok0) {
            atomicAdd(&g_aggr[(size_t)d0 * 128 + c0],     m00);
            atomicAdd(&g_aggr[(size_t)d0 * 128 + c0 + 1], m01);
            atomicAdd(&g_aggr[(size_t)d0 * 128 + c1],     m20);
            atomicAdd(&g_aggr[(size_t)d0 * 128 + c1 + 1], m21);
        }
        if (ok1) {
            atomicAdd(&g_aggr[(size_t)d1 * 128 + c0],     m10);
            atomicAdd(&g_aggr[(size_t)d1 * 128 + c0 + 1], m11);
            atomicAdd(&g_aggr[(size_t)d1 * 128 + c1],     m30);
            atomicAdd(&g_aggr[(size_t)d1 * 128 + c1 + 1], m31);
        }
    }

    // ---- coord MLP L1: acc3 = m @ cW1 (N=64) ----
    cp_wait<0>(); __syncthreads();
    float acc3[8][4];
    #pragma unroll
    for (int n = 0; n < 8; n++)
        #pragma unroll
        for (int j = 0; j < 4; j++) acc3[n][j] = 0.0f;
    gemm_regA<4>(acc3, am, As_b, As_b + 64 * SC * 2, SC, a_row, a_koff);

    // ---- w = silu(acc3 + cb1) . cW2 + cb2 ; quad shuffle-reduce ; scatter ----
    float p1 = 0.0f, p2 = 0.0f;
    #pragma unroll
    for (int t = 0; t < 8; t++) {
        int c = 8 * t + 2 * tig;
        float b0 = cb1[c], b1 = cb1[c + 1];
        float w0 = cW2[c], w1 = cW2[c + 1];
        p1 += silu_f(acc3[t][0] + b0) * w0 + silu_f(acc3[t][1] + b1) * w1;
        p2 += silu_f(acc3[t][2] + b0) * w0 + silu_f(acc3[t][3] + b1) * w1;
    }
    p1 += __shfl_xor_sync(0xffffffffu, p1, 1);
    p1 += __shfl_xor_sync(0xffffffffu, p1, 2);
    p2 += __shfl_xor_sync(0xffffffffu, p2, 1);
    p2 += __shfl_xor_sync(0xffffffffu, p2, 2);
    if (tig < 2) {
        int r = (tig == 0) ? r0 : r1;
        float w = ((tig == 0) ? p1 : p2) + cb2[0];
        if (e0 + r < E) {
            int s = sidx[r], d = didx[r];
            float dx = coords[(size_t)s * 3 + 0] - coords[(size_t)d * 3 + 0];
            float dy = coords[(size_t)s * 3 + 1] - coords[(size_t)d * 3 + 1];
            float dz = coords[(size_t)s * 3 + 2] - coords[(size_t)d * 3 + 2];
            float nrm = sqrtf(dx * dx + dy * dy + dz * dz) + 1e-8f;
            float scl = w / nrm;
            atomicAdd(&g_cacc[(size_t)d * 3 + 0], dx * scl);
            atomicAdd(&g_cacc[(size_t)d * 3 + 1], dy * scl);
            atomicAdd(&g_cacc[(size_t)d * 3 + 2], dz * scl);
        }
    }
    #undef ISSUE_A_NF
    #undef ISSUE_B_EW1
}

// ---------------------------------------------------------------------------
// Node kernel: 128-node tile; same register-chained structure.
// ---------------------------------------------------------------------------
__global__ __launch_bounds__(256, 2)
void node_kernel(const float* __restrict__ node_feat,
                 const float* __restrict__ coords,
                 const float* __restrict__ nb1,
                 const float* __restrict__ nb2,
                 float* __restrict__ out_nodes,
                 float* __restrict__ out_coords,
                 int N)
{
    extern __shared__ __half smh[];
    __half* As  = smh;                        // 2 x 9216
    __half* Bs  = smh + 2 * 128 * SA;         // 2 x 8704
    __half* W2s = Bs + 2 * 64 * SB;           // 2 x 8704

    const int tid  = threadIdx.x;
    const int n0   = blockIdx.x * 128;
    const int lane = tid & 31;
    const int wid  = tid >> 5;
    const int g    = lane >> 2;
    const int tig  = lane & 3;
    const int RW   = wid * 16;

    const unsigned As_b  = ssa(As);
    const unsigned Bs_b  = ssa(Bs);
    const unsigned W2s_b = ssa(W2s);
    const int a_row  = lane & 15;
    const int a_koff = (lane >> 4) * 8;

    #define N_ISSUE_A(T, BUF) do {                                           \
        const __half* src = ((T) < 2) ? g_nf_h : g_ag_h;                     \
        int cb = ((T) & 1) * 64;                                             \
        unsigned dstb = As_b + (BUF) * 128 * SA * 2;                         \
        _Pragma("unroll")                                                    \
        for (int q = 0; q < 4; q++) {                                        \
            int i = tid + q * 256;                                           \
            int e = i >> 3, v = i & 7;                                       \
            int n = n0 + e; if (n >= N) n = N - 1;                           \
            cp16(dstb + (e * SA + v * 8) * 2,                                \
                 &src[(size_t)n * 128 + cb + v * 8]);                        \
        }                                                                    \
    } while (0)

    #define N_ISSUE_B(T, BUF) do {                                           \
        unsigned dstb = Bs_b + (BUF) * 64 * SB * 2;                          \
        _Pragma("unroll")                                                    \
        for (int q = 0; q < 4; q++) {                                        \
            int i = tid + q * 256;                                           \
            int k = i >> 4, v = i & 15;                                      \
            cp16(dstb + (k * SB + v * 8) * 2,                                \
                 &g_w_h[OFF_NW1 + (size_t)((T) * 64 + k) * 128 + v * 8]);    \
        }                                                                    \
    } while (0)

    N_ISSUE_A(0, 0); N_ISSUE_B(0, 0); cp_commit();             // T0
    #pragma unroll
    for (int q = 0; q < 8; q++) {                              // W2 (nW2)
        int i = tid + q * 256;
        int jj = i >> 10, i2 = i & 1023;
        int k = i2 >> 4, v = i2 & 15;
        cp16(W2s_b + (jj * 64 * SB + k * SB + v * 8) * 2,
             &g_w_h[OFF_NW2 + (size_t)(jj * 64 + k) * 128 + v * 8]);
    }
    cp_commit();                                               // W2

    float acc[16][4];
    #pragma unroll
    for (int n = 0; n < 16; n++)
        #pragma unroll
        for (int j = 0; j < 4; j++) acc[n][j] = 0.0f;

    const unsigned aw0 = As_b + RW * SA * 2;
    const unsigned aw1 = As_b + (128 * SA + RW * SA) * 2;
    const unsigned bb0 = Bs_b;
    const unsigned bb1 = Bs_b + 64 * SB * 2;

    // t=0
    N_ISSUE_A(1, 1); N_ISSUE_B(1, 1); cp_commit();             // T1
    cp_wait<2>(); __syncthreads();
    gemm_k64<8>(acc, aw0, SA, bb0, SB, a_row, a_koff);
    __syncthreads();
    // t=1
    N_ISSUE_A(2, 0); N_ISSUE_B(2, 0); cp_commit();             // T2
    cp_wait<1>(); __syncthreads();
    gemm_k64<8>(acc, aw1, SA, bb1, SB, a_row, a_koff);
    __syncthreads();
    // t=2
    N_ISSUE_A(3, 1); N_ISSUE_B(3, 1); cp_commit();             // T3
    cp_wait<1>(); __syncthreads();
    gemm_k64<8>(acc, aw0, SA, bb0, SB, a_row, a_koff);
    __syncthreads();
    // t=3
    cp_wait<0>(); __syncthreads();
    gemm_k64<8>(acc, aw1, SA, bb1, SB, a_row, a_koff);

    // pack h = silu(acc + nb1) -> layer2 A frags
    unsigned ah[8][4];
    #pragma unroll
    for (int j = 0; j < 8; j++) {
        int c0 = 16 * j + 2 * tig;
        int c1 = c0 + 8;
        float b00 = nb1[c0], b01 = nb1[c0 + 1];
        float b10 = nb1[c1], b11 = nb1[c1 + 1];
        ah[j][0] = pack2(silu_f(acc[2*j][0] + b00),   silu_f(acc[2*j][1] + b01));
        ah[j][1] = pack2(silu_f(acc[2*j][2] + b00),   silu_f(acc[2*j][3] + b01));
        ah[j][2] = pack2(silu_f(acc[2*j+1][0] + b10), silu_f(acc[2*j+1][1] + b11));
        ah[j][3] = pack2(silu_f(acc[2*j+1][2] + b10), silu_f(acc[2*j+1][3] + b11));
    }

    // layer 2: A in regs, B resident in W2s
    float acc2[16][4];
    #pragma unroll
    for (int n = 0; n < 16; n++)
        #pragma unroll
        for (int j = 0; j < 4; j++) acc2[n][j] = 0.0f;
    gemm_regA<8>(acc2, ah, W2s_b, W2s_b + 64 * SB * 2, SB, a_row, a_koff);

    // residual epilogue
    const int r0 = RW + g, r1 = RW + g + 8;
    const int nn0 = n0 + r0, nn1 = n0 + r1;
    #pragma unroll
    for (int j = 0; j < 8; j++) {
        int c0 = 16 * j + 2 * tig;
        int c1 = c0 + 8;
        if (nn0 < N) {
            out_nodes[(size_t)nn0 * 128 + c0] =
                node_feat[(size_t)nn0 * 128 + c0] + acc2[2*j][0] + nb2[c0];
            out_nodes[(size_t)nn0 * 128 + c0 + 1] =
                node_feat[(size_t)nn0 * 128 + c0 + 1] + acc2[2*j][1] + nb2[c0 + 1];
            out_nodes[(size_t)nn0 * 128 + c1] =
                node_feat[(size_t)nn0 * 128 + c1] + acc2[2*j+1][0] + nb2[c1];
            out_nodes[(size_t)nn0 * 128 + c1 + 1] =
                node_feat[(size_t)nn0 * 128 + c1 + 1] + acc2[2*j+1][1] + nb2[c1 + 1];
        }
        if (nn1 < N) {
            out_nodes[(size_t)nn1 * 128 + c0] =
                node_feat[(size_t)nn1 * 128 + c0] + acc2[2*j][2] + nb2[c0];
            out_nodes[(size_t)nn1 * 128 + c0 + 1] =
                node_feat[(size_t)nn1 * 128 + c0 + 1] + acc2[2*j][3] + nb2[c0 + 1];
            out_nodes[(size_t)nn1 * 128 + c1] =
                node_feat[(size_t)nn1 * 128 + c1] + acc2[2*j+1][2] + nb2[c1];
            out_nodes[(size_t)nn1 * 128 + c1 + 1] =
                node_feat[(size_t)nn1 * 128 + c1 + 1] + acc2[2*j+1][3] + nb2[c1 + 1];
        }
    }
    // coords
    for (int i = tid; i < 128 * 3; i += 256) {
        int e = i / 3, d = i % 3;
        int n = n0 + e;
        if (n < N)
            out_coords[(size_t)n * 3 + d] =
                coords[(size_t)n * 3 + d] + g_cacc[(size_t)n * 3 + d];
    }
    #undef N_ISSUE_A
    #undef N_ISSUE_B
}

// ---------------------------------------------------------------------------
extern "C" void kernel_launch(void* const* d_in, const int* in_sizes, int n_in,
                              void* d_out, int out_size)
{
    const float* node_feat = (const float*)d_in[0];
    const int*   eidx      = (const int*)  d_in[1];
    const float* edge_attr = (const float*)d_in[2];
    const float* coords    = (const float*)d_in[3];
    const float* eW1 = (const float*)d_in[4];
    const float* eb1 = (const float*)d_in[5];
    const float* eW2 = (const float*)d_in[6];
    const float* eb2 = (const float*)d_in[7];
    const float* nW1 = (const float*)d_in[8];
    const float* nb1 = (const float*)d_in[9];
    const float* nW2 = (const float*)d_in[10];
    const float* nb2 = (const float*)d_in[11];
    const float* cW1 = (const float*)d_in[12];
    const float* cb1 = (const float*)d_in[13];
    const float* cW2 = (const float*)d_in[14];
    const float* cb2 = (const float*)d_in[15];

    const int N = in_sizes[0] / NODE_DIM;
    const int E = in_sizes[1] / 2;
    const int* esrc = eidx;
    const int* edst = eidx + E;

    float* out_nodes  = (float*)d_out;
    float* out_coords = out_nodes + (size_t)N * NODE_DIM;

    constexpr int EDGE_SMEM = (2 * 128 * SA + 4 * 64 * SB) * 2 + 256 * 4; // 107,520 B
    constexpr int NODE_SMEM = (2 * 128 * SA + 4 * 64 * SB) * 2;          // 106,496 B
    cudaFuncSetAttribute(edge_kernel, cudaFuncAttributeMaxDynamicSharedMemorySize, EDGE_SMEM);
    cudaFuncSetAttribute(node_kernel, cudaFuncAttributeMaxDynamicSharedMemorySize, NODE_SMEM);

    prep_kernel<<<(N * NODE_DIM + 255) / 256, 256>>>(node_feat, eW1, eW2, cW1, nW1, nW2, N);

    edge_kernel<<<(E + 127) / 128, 256, EDGE_SMEM>>>(
        esrc, edst, edge_attr, coords, eb1, eb2, cb1, cW2, cb2, E);

    cvt_aggr_kernel<<<(N * HID + 255) / 256, 256>>>(N * HID);

    node_kernel<<<(N + 127) / 128, 256, NODE_SMEM>>>(
        node_feat, coords, nb1, nb2, out_nodes, out_coords, N);
}

// round 14
// speedup vs baseline: 5.4395x; 1.0184x over previous
#include <cuda_runtime.h>
#include <cuda_fp16.h>
#include <math.h>

// Problem constants (fixed by the dataset)
#define MAXN 20000
#define NODE_DIM 128
#define EDGE_DIM 64
#define HID 128

// Weight offsets in half scratch
#define OFF_EW1 0            // 320*128
#define OFF_EW2 40960        // 128*128
#define OFF_CW1 57344        // 128*64
#define OFF_NW1 65536        // 256*128
#define OFF_NW2 98304        // 128*128
#define W_TOTAL 114688

// Shared strides (halves): all == 8 (mod 64) halves -> conflict-free ldmatrix
#define SA 72
#define SB 136
#define SC 72

// Scratch (device globals: no allocation allowed)
__device__ float  g_aggr[(size_t)MAXN * HID];      // segment-summed messages (fp32)
__device__ float  g_cacc[(size_t)MAXN * 3];        // coord update accumulator
__device__ __half g_nf_h[(size_t)MAXN * NODE_DIM]; // node_feat in half
__device__ __half g_ag_h[(size_t)MAXN * HID];      // aggr in half (post-edge)
__device__ __half g_w_h[W_TOTAL];                  // all GEMM weights in half

__device__ __forceinline__ float silu_f(float x) {
    return x / (1.0f + __expf(-x));
}
__device__ __forceinline__ unsigned ssa(const void* p) {
    return (unsigned)__cvta_generic_to_shared(p);
}
__device__ __forceinline__ unsigned pack2(float x, float y) {
    __half2 h = __floats2half2_rn(x, y);
    return *(unsigned*)&h;
}
__device__ __forceinline__ void cp16(unsigned saddr, const void* g) {
    asm volatile("cp.async.ca.shared.global [%0], [%1], 16;" :: "r"(saddr), "l"(g));
}
__device__ __forceinline__ void cp_commit() {
    asm volatile("cp.async.commit_group;");
}
template <int N>
__device__ __forceinline__ void cp_wait() {
    asm volatile("cp.async.wait_group %0;" :: "n"(N));
}
__device__ __forceinline__ void red_v4(float* p, float a, float b, float c, float d) {
    asm volatile("red.global.add.v4.f32 [%0], {%1,%2,%3,%4};"
                 :: "l"(p), "f"(a), "f"(b), "f"(c), "f"(d) : "memory");
}
__device__ __forceinline__ void ldsm_x4(unsigned addr, unsigned& r0, unsigned& r1,
                                        unsigned& r2, unsigned& r3) {
    asm volatile("ldmatrix.sync.aligned.m8n8.x4.shared.b16 {%0,%1,%2,%3}, [%4];"
                 : "=r"(r0), "=r"(r1), "=r"(r2), "=r"(r3) : "r"(addr));
}
__device__ __forceinline__ void ldsm_x4_t(unsigned addr, unsigned& r0, unsigned& r1,
                                          unsigned& r2, unsigned& r3) {
    asm volatile("ldmatrix.sync.aligned.m8n8.x4.trans.shared.b16 {%0,%1,%2,%3}, [%4];"
                 : "=r"(r0), "=r"(r1), "=r"(r2), "=r"(r3) : "r"(addr));
}
__device__ __forceinline__ void mma_f16(float* c, unsigned a0, unsigned a1,
                                        unsigned a2, unsigned a3,
                                        unsigned b0, unsigned b1) {
    asm volatile("mma.sync.aligned.m16n8k16.row.col.f32.f16.f16.f32 "
                 "{%0,%1,%2,%3}, {%4,%5,%6,%7}, {%8,%9}, {%0,%1,%2,%3};"
                 : "+f"(c[0]), "+f"(c[1]), "+f"(c[2]), "+f"(c[3])
                 : "r"(a0), "r"(a1), "r"(a2), "r"(a3), "r"(b0), "r"(b1));
}

// GEMM over one staged k64 tile: A from smem (ldmatrix), warp rows fixed.
// NP = number of 16-col B pairs (NP=8 -> N=128).
template <int NP>
__device__ __forceinline__ void gemm_k64(float (*acc)[4], unsigned a_base, int sa,
                                         unsigned b_base, int sb,
                                         int a_row, int a_koff) {
    #pragma unroll
    for (int ks = 0; ks < 4; ks++) {
        unsigned a0, a1, a2, a3;
        ldsm_x4(a_base + (a_row * sa + ks * 16 + a_koff) * 2, a0, a1, a2, a3);
        #pragma unroll
        for (int p = 0; p < NP; p++) {
            unsigned b0, b1, b2, b3;
            ldsm_x4_t(b_base + ((ks * 16 + a_row) * sb + p * 16 + a_koff) * 2,
                      b0, b1, b2, b3);
            mma_f16(acc[2 * p],     a0, a1, a2, a3, b0, b1);
            mma_f16(acc[2 * p + 1], a0, a1, a2, a3, b2, b3);
        }
    }
}

// GEMM with A in registers (8 k16 fragments), B from two 64-row smem buffers.
template <int NP>
__device__ __forceinline__ void gemm_regA(float (*acc)[4], const unsigned (*af)[4],
                                          unsigned b_buf0, unsigned b_buf1, int sb,
                                          int a_row, int a_koff) {
    #pragma unroll
    for (int j = 0; j < 8; j++) {
        unsigned base = (j < 4) ? b_buf0 : b_buf1;
        int lr = (j & 3) * 16;
        #pragma unroll
        for (int p = 0; p < NP; p++) {
            unsigned b0, b1, b2, b3;
            ldsm_x4_t(base + ((lr + a_row) * sb + p * 16 + a_koff) * 2,
                      b0, b1, b2, b3);
            mma_f16(acc[2 * p],     af[j][0], af[j][1], af[j][2], af[j][3], b0, b1);
            mma_f16(acc[2 * p + 1], af[j][0], af[j][1], af[j][2], af[j][3], b2, b3);
        }
    }
}

// ---------------------------------------------------------------------------
// Prep: zero scratch, convert node_feat + all weights to half
// ---------------------------------------------------------------------------
__global__ void prep_kernel(const float* __restrict__ node_feat,
                            const float* __restrict__ eW1,
                            const float* __restrict__ eW2,
                            const float* __restrict__ cW1,
                            const float* __restrict__ nW1,
                            const float* __restrict__ nW2,
                            int N)
{
    int i = blockIdx.x * blockDim.x + threadIdx.x;
    int nf = N * NODE_DIM;
    if (i < nf) {
        g_aggr[i] = 0.0f;
        g_nf_h[i] = __float2half_rn(node_feat[i]);
    }
    if (i < N * 3) g_cacc[i] = 0.0f;
    if (i < W_TOTAL) {
        float v;
        if      (i < OFF_EW2) v = eW1[i - OFF_EW1];
        else if (i < OFF_CW1) v = eW2[i - OFF_EW2];
        else if (i < OFF_NW1) v = cW1[i - OFF_CW1];
        else if (i < OFF_NW2) v = nW1[i - OFF_NW1];
        else                  v = nW2[i - OFF_NW2];
        g_w_h[i] = __float2half_rn(v);
    }
}

// Convert aggregated messages to half (runs after edge kernel)
__global__ void cvt_aggr_kernel(int n) {
    int i = blockIdx.x * blockDim.x + threadIdx.x;
    if (i < n) g_ag_h[i] = __float2half_rn(g_aggr[i]);
}

// ---------------------------------------------------------------------------
// Edge kernel: 128-edge tile; warp = 16 edges x full width.
// Layers chained in registers; cp.async double-buffered pipeline.
// Aggregation scatter uses quad-shuffle regrouping + red.global.add.v4.f32
// (4x fewer LSU ops and LTS atomic transactions than scalar atomicAdd).
// ---------------------------------------------------------------------------
__global__ __launch_bounds__(256, 2)
void edge_kernel(const int*   __restrict__ esrc,
                 const int*   __restrict__ edst,
                 const float* __restrict__ edge_attr,
                 const float* __restrict__ coords,
                 const float* __restrict__ eb1,
                 const float* __restrict__ eb2,
                 const float* __restrict__ cb1,
                 const float* __restrict__ cW2,
                 const float* __restrict__ cb2,
                 int E)
{
    extern __shared__ __half smh[];
    __half* As  = smh;                        // 2 x 9216
    __half* Bs  = smh + 2 * 128 * SA;         // 2 x 8704
    __half* W2s = Bs + 2 * 64 * SB;           // 2 x 8704
    int* sidx = (int*)(W2s + 2 * 64 * SB);    // 128
    int* didx = sidx + 128;                   // 128

    const int tid  = threadIdx.x;
    const int e0   = blockIdx.x * 128;
    const int lane = tid & 31;
    const int wid  = tid >> 5;
    const int g    = lane >> 2;
    const int tig  = lane & 3;
    const int RW   = wid * 16;                // warp's 16 rows

    const unsigned As_b  = ssa(As);
    const unsigned Bs_b  = ssa(Bs);
    const unsigned W2s_b = ssa(W2s);
    const int a_row  = lane & 15;
    const int a_koff = (lane >> 4) * 8;

    if (tid < 128) {
        int e = e0 + tid; if (e >= E) e = E - 1;
        sidx[tid] = esrc[e];
        didx[tid] = edst[e];
    }
    __syncthreads();

    // A tile: 128 rows x 64 halves -> 1024 cp16 (4 per thread)
    #define ISSUE_A_NF(T, BUF) do {                                          \
        const int* idxp = ((T) < 2) ? sidx : didx;                           \
        int cb = ((T) & 1) * 64;                                             \
        unsigned dstb = As_b + (BUF) * 128 * SA * 2;                         \
        _Pragma("unroll")                                                    \
        for (int q = 0; q < 4; q++) {                                        \
            int i = tid + q * 256;                                           \
            int e = i >> 3, v = i & 7;                                       \
            cp16(dstb + (e * SA + v * 8) * 2,                                \
                 &g_nf_h[(size_t)idxp[e] * 128 + cb + v * 8]);               \
        }                                                                    \
    } while (0)

    // B tile: 64 rows x 128 halves -> 1024 cp16 (4 per thread)
    #define ISSUE_B_EW1(T, BUF) do {                                         \
        unsigned dstb = Bs_b + (BUF) * 64 * SB * 2;                          \
        _Pragma("unroll")                                                    \
        for (int q = 0; q < 4; q++) {                                        \
            int i = tid + q * 256;                                           \
            int k = i >> 4, v = i & 15;                                      \
            cp16(dstb + (k * SB + v * 8) * 2,                                \
                 &g_w_h[OFF_EW1 + (size_t)((T) * 64 + k) * 128 + v * 8]);    \
        }                                                                    \
    } while (0)

    // prologue: T0, then eW2 (2 tiles x 64 x 128 halves -> 2048 cp16)
    ISSUE_A_NF(0, 0); ISSUE_B_EW1(0, 0); cp_commit();          // T0
    #pragma unroll
    for (int q = 0; q < 8; q++) {                              // W2 group
        int i = tid + q * 256;
        int jj = i >> 10, i2 = i & 1023;
        int k = i2 >> 4, v = i2 & 15;
        cp16(W2s_b + (jj * 64 * SB + k * SB + v * 8) * 2,
             &g_w_h[OFF_EW2 + (size_t)(jj * 64 + k) * 128 + v * 8]);
    }
    cp_commit();                                               // W2

    float acc[16][4];
    #pragma unroll
    for (int n = 0; n < 16; n++)
        #pragma unroll
        for (int j = 0; j < 4; j++) acc[n][j] = 0.0f;

    const unsigned aw0 = As_b + RW * SA * 2;                   // warp A base buf0
    const unsigned aw1 = As_b + (128 * SA + RW * SA) * 2;      // buf1
    const unsigned bb0 = Bs_b;
    const unsigned bb1 = Bs_b + 64 * SB * 2;

    // ---- t=0 ----
    ISSUE_A_NF(1, 1); ISSUE_B_EW1(1, 1); cp_commit();          // T1
    cp_wait<2>(); __syncthreads();
    gemm_k64<8>(acc, aw0, SA, bb0, SB, a_row, a_koff);
    __syncthreads();
    // ---- t=1 ----
    ISSUE_A_NF(2, 0); ISSUE_B_EW1(2, 0); cp_commit();          // T2
    cp_wait<1>(); __syncthreads();
    gemm_k64<8>(acc, aw1, SA, bb1, SB, a_row, a_koff);
    __syncthreads();
    // ---- t=2 ----
    ISSUE_A_NF(3, 1); ISSUE_B_EW1(3, 1); cp_commit();          // T3
    cp_wait<1>(); __syncthreads();
    gemm_k64<8>(acc, aw0, SA, bb0, SB, a_row, a_koff);
    __syncthreads();
    // ---- t=3: attr tile (plain ld+cvt+sts into A buf0) + eW1 tile4 async ----
    {
        #pragma unroll
        for (int q = 0; q < 8; q++) {
            int i = tid + q * 256;
            int e = i >> 4, v = i & 15;
            int ee = e0 + e; if (ee >= E) ee = E - 1;
            float4 f = *(const float4*)&edge_attr[(size_t)ee * 64 + v * 4];
            *(__half2*)&As[e * SA + v * 4]     = __floats2half2_rn(f.x, f.y);
            *(__half2*)&As[e * SA + v * 4 + 2] = __floats2half2_rn(f.z, f.w);
        }
        ISSUE_B_EW1(4, 0); cp_commit();                        // B4
    }
    cp_wait<1>(); __syncthreads();
    gemm_k64<8>(acc, aw1, SA, bb1, SB, a_row, a_koff);
    __syncthreads();
    // ---- t=4 ----
    cp_wait<0>(); __syncthreads();
    gemm_k64<8>(acc, aw0, SA, bb0, SB, a_row, a_koff);
    __syncthreads();

    // ---- pack h1 = silu(acc + eb1) into layer-2 A fragments (registers) ----
    unsigned ah[8][4];
    #pragma unroll
    for (int j = 0; j < 8; j++) {
        int c0 = 16 * j + 2 * tig;
        int c1 = c0 + 8;
        float b00 = eb1[c0], b01 = eb1[c0 + 1];
        float b10 = eb1[c1], b11 = eb1[c1 + 1];
        ah[j][0] = pack2(silu_f(acc[2*j][0] + b00),   silu_f(acc[2*j][1] + b01));
        ah[j][1] = pack2(silu_f(acc[2*j][2] + b00),   silu_f(acc[2*j][3] + b01));
        ah[j][2] = pack2(silu_f(acc[2*j+1][0] + b10), silu_f(acc[2*j+1][1] + b11));
        ah[j][3] = pack2(silu_f(acc[2*j+1][2] + b10), silu_f(acc[2*j+1][3] + b11));
    }

    // prefetch cW1 into As region (free now): 2 tiles x 64 x 64 halves -> 1024 cp16
    #pragma unroll
    for (int q = 0; q < 4; q++) {
        int i = tid + q * 256;
        int jj = i >> 9, i2 = i & 511;
        int k = i2 >> 3, v = i2 & 7;
        cp16(As_b + (jj * 64 * SC + k * SC + v * 8) * 2,
             &g_w_h[OFF_CW1 + (size_t)(jj * 64 + k) * 64 + v * 8]);
    }
    cp_commit();                                               // C1

    // ---- layer 2: acc2 = h1 @ eW2 (A in regs, B resident in W2s) ----
    float acc2[16][4];
    #pragma unroll
    for (int n = 0; n < 16; n++)
        #pragma unroll
        for (int j = 0; j < 4; j++) acc2[n][j] = 0.0f;
    gemm_regA<8>(acc2, ah, W2s_b, W2s_b + 64 * SB * 2, SB, a_row, a_koff);

    // ---- m = silu(acc2 + eb2): pack coord-A frags + vectorized red scatter ----
    unsigned am[8][4];
    const int r0 = RW + g, r1 = RW + g + 8;
    const bool ok0 = (e0 + r0) < E, ok1 = (e0 + r1) < E;
    const int d0 = didx[r0], d1 = didx[r1];
    const int odd = tig & 1;
    // v4 column base within each 16-col group: even lanes cover the low 8
    // columns (16j + 2*tig), odd lanes the high 8 (16j + 2*tig + 6).
    const int cbase_off = 2 * tig + (odd ? 6 : 0);
    float* rowp0 = &g_aggr[(size_t)d0 * 128];
    float* rowp1 = &g_aggr[(size_t)d1 * 128];
    #pragma unroll
    for (int j = 0; j < 8; j++) {
        int c0 = 16 * j + 2 * tig;
        int c1 = c0 + 8;
        float b00 = eb2[c0], b01 = eb2[c0 + 1];
        float b10 = eb2[c1], b11 = eb2[c1 + 1];
        float m00 = silu_f(acc2[2*j][0] + b00),   m01 = silu_f(acc2[2*j][1] + b01);
        float m10 = silu_f(acc2[2*j][2] + b00),   m11 = silu_f(acc2[2*j][3] + b01);
        float m20 = silu_f(acc2[2*j+1][0] + b10), m21 = silu_f(acc2[2*j+1][1] + b11);
        float m30 = silu_f(acc2[2*j+1][2] + b10), m31 = silu_f(acc2[2*j+1][3] + b11);
        am[j][0] = pack2(m00, m01);
        am[j][1] = pack2(m10, m11);
        am[j][2] = pack2(m20, m21);
        am[j][3] = pack2(m30, m31);

        int col = 16 * j + cbase_off;
        // row r0: exchange within lane pair (tig^1): even sends its high-tile
        // pair (m20,m21) and receives partner's low-tile pair; odd vice versa.
        {
            float sx = odd ? m00 : m20;
            float sy = odd ? m01 : m21;
            float rx = __shfl_xor_sync(0xffffffffu, sx, 1);
            float ry = __shfl_xor_sync(0xffffffffu, sy, 1);
            float v0 = odd ? rx : m00, v1 = odd ? ry : m01;
            float v2 = odd ? m20 : rx, v3 = odd ? m21 : ry;
            if (ok0) red_v4(rowp0 + col, v0, v1, v2, v3);
        }
        // row r1
        {
            float sx = odd ? m10 : m30;
            float sy = odd ? m11 : m31;
            float rx = __shfl_xor_sync(0xffffffffu, sx, 1);
            float ry = __shfl_xor_sync(0xffffffffu, sy, 1);
            float v0 = odd ? rx : m10, v1 = odd ? ry : m11;
            float v2 = odd ? m30 : rx, v3 = odd ? m31 : ry;
            if (ok1) red_v4(rowp1 + col, v0, v1, v2, v3);
        }
    }

    // ---- coord MLP L1: acc3 = m @ cW1 (N=64) ----
    cp_wait<0>(); __syncthreads();
    float acc3[8][4];
    #pragma unroll
    for (int n = 0; n < 8; n++)
        #pragma unroll
        for (int j = 0; j < 4; j++) acc3[n][j] = 0.0f;
    gemm_regA<4>(acc3, am, As_b, As_b + 64 * SC * 2, SC, a_row, a_koff);

    // ---- w = silu(acc3 + cb1) . cW2 + cb2 ; quad shuffle-reduce ; scatter ----
    float p1 = 0.0f, p2 = 0.0f;
    #pragma unroll
    for (int t = 0; t < 8; t++) {
        int c = 8 * t + 2 * tig;
        float b0 = cb1[c], b1 = cb1[c + 1];
        float w0 = cW2[c], w1 = cW2[c + 1];
        p1 += silu_f(acc3[t][0] + b0) * w0 + silu_f(acc3[t][1] + b1) * w1;
        p2 += silu_f(acc3[t][2] + b0) * w0 + silu_f(acc3[t][3] + b1) * w1;
    }
    p1 += __shfl_xor_sync(0xffffffffu, p1, 1);
    p1 += __shfl_xor_sync(0xffffffffu, p1, 2);
    p2 += __shfl_xor_sync(0xffffffffu, p2, 1);
    p2 += __shfl_xor_sync(0xffffffffu, p2, 2);
    if (tig < 2) {
        int r = (tig == 0) ? r0 : r1;
        float w = ((tig == 0) ? p1 : p2) + cb2[0];
        if (e0 + r < E) {
            int s = sidx[r], d = didx[r];
            float dx = coords[(size_t)s * 3 + 0] - coords[(size_t)d * 3 + 0];
            float dy = coords[(size_t)s * 3 + 1] - coords[(size_t)d * 3 + 1];
            float dz = coords[(size_t)s * 3 + 2] - coords[(size_t)d * 3 + 2];
            float nrm = sqrtf(dx * dx + dy * dy + dz * dz) + 1e-8f;
            float scl = w / nrm;
            atomicAdd(&g_cacc[(size_t)d * 3 + 0], dx * scl);
            atomicAdd(&g_cacc[(size_t)d * 3 + 1], dy * scl);
            atomicAdd(&g_cacc[(size_t)d * 3 + 2], dz * scl);
        }
    }
    #undef ISSUE_A_NF
    #undef ISSUE_B_EW1
}

// ---------------------------------------------------------------------------
// Node kernel: 128-node tile; same register-chained structure.
// ---------------------------------------------------------------------------
__global__ __launch_bounds__(256, 2)
void node_kernel(const float* __restrict__ node_feat,
                 const float* __restrict__ coords,
                 const float* __restrict__ nb1,
                 const float* __restrict__ nb2,
                 float* __restrict__ out_nodes,
                 float* __restrict__ out_coords,
                 int N)
{
    extern __shared__ __half smh[];
    __half* As  = smh;                        // 2 x 9216
    __half* Bs  = smh + 2 * 128 * SA;         // 2 x 8704
    __half* W2s = Bs + 2 * 64 * SB;           // 2 x 8704

    const int tid  = threadIdx.x;
    const int n0   = blockIdx.x * 128;
    const int lane = tid & 31;
    const int wid  = tid >> 5;
    const int g    = lane >> 2;
    const int tig  = lane & 3;
    const int RW   = wid * 16;

    const unsigned As_b  = ssa(As);
    const unsigned Bs_b  = ssa(Bs);
    const unsigned W2s_b = ssa(W2s);
    const int a_row  = lane & 15;
    const int a_koff = (lane >> 4) * 8;

    #define N_ISSUE_A(T, BUF) do {                                           \
        const __half* src = ((T) < 2) ? g_nf_h : g_ag_h;                     \
        int cb = ((T) & 1) * 64;                                             \
        unsigned dstb = As_b + (BUF) * 128 * SA * 2;                         \
        _Pragma("unroll")                                                    \
        for (int q = 0; q < 4; q++) {                                        \
            int i = tid + q * 256;                                           \
            int e = i >> 3, v = i & 7;                                       \
            int n = n0 + e; if (n >= N) n = N - 1;                           \
            cp16(dstb + (e * SA + v * 8) * 2,                                \
                 &src[(size_t)n * 128 + cb + v * 8]);                        \
        }                                                                    \
    } while (0)

    #define N_ISSUE_B(T, BUF) do {                                           \
        unsigned dstb = Bs_b + (BUF) * 64 * SB * 2;                          \
        _Pragma("unroll")                                                    \
        for (int q = 0; q < 4; q++) {                                        \
            int i = tid + q * 256;                                           \
            int k = i >> 4, v = i & 15;                                      \
            cp16(dstb + (k * SB + v * 8) * 2,                                \
                 &g_w_h[OFF_NW1 + (size_t)((T) * 64 + k) * 128 + v * 8]);    \
        }                                                                    \
    } while (0)

    N_ISSUE_A(0, 0); N_ISSUE_B(0, 0); cp_commit();             // T0
    #pragma unroll
    for (int q = 0; q < 8; q++) {                              // W2 (nW2)
        int i = tid + q * 256;
        int jj = i >> 10, i2 = i & 1023;
        int k = i2 >> 4, v = i2 & 15;
        cp16(W2s_b + (jj * 64 * SB + k * SB + v * 8) * 2,
             &g_w_h[OFF_NW2 + (size_t)(jj * 64 + k) * 128 + v * 8]);
    }
    cp_commit();                                               // W2

    float acc[16][4];
    #pragma unroll
    for (int n = 0; n < 16; n++)
        #pragma unroll
        for (int j = 0; j < 4; j++) acc[n][j] = 0.0f;

    const unsigned aw0 = As_b + RW * SA * 2;
    const unsigned aw1 = As_b + (128 * SA + RW * SA) * 2;
    const unsigned bb0 = Bs_b;
    const unsigned bb1 = Bs_b + 64 * SB * 2;

    // t=0
    N_ISSUE_A(1, 1); N_ISSUE_B(1, 1); cp_commit();             // T1
    cp_wait<2>(); __syncthreads();
    gemm_k64<8>(acc, aw0, SA, bb0, SB, a_row, a_koff);
    __syncthreads();
    // t=1
    N_ISSUE_A(2, 0); N_ISSUE_B(2, 0); cp_commit();             // T2
    cp_wait<1>(); __syncthreads();
    gemm_k64<8>(acc, aw1, SA, bb1, SB, a_row, a_koff);
    __syncthreads();
    // t=2
    N_ISSUE_A(3, 1); N_ISSUE_B(3, 1); cp_commit();             // T3
    cp_wait<1>(); __syncthreads();
    gemm_k64<8>(acc, aw0, SA, bb0, SB, a_row, a_koff);
    __syncthreads();
    // t=3
    cp_wait<0>(); __syncthreads();
    gemm_k64<8>(acc, aw1, SA, bb1, SB, a_row, a_koff);

    // pack h = silu(acc + nb1) -> layer2 A frags
    unsigned ah[8][4];
    #pragma unroll
    for (int j = 0; j < 8; j++) {
        int c0 = 16 * j + 2 * tig;
        int c1 = c0 + 8;
        float b00 = nb1[c0], b01 = nb1[c0 + 1];
        float b10 = nb1[c1], b11 = nb1[c1 + 1];
        ah[j][0] = pack2(silu_f(acc[2*j][0] + b00),   silu_f(acc[2*j][1] + b01));
        ah[j][1] = pack2(silu_f(acc[2*j][2] + b00),   silu_f(acc[2*j][3] + b01));
        ah[j][2] = pack2(silu_f(acc[2*j+1][0] + b10), silu_f(acc[2*j+1][1] + b11));
        ah[j][3] = pack2(silu_f(acc[2*j+1][2] + b10), silu_f(acc[2*j+1][3] + b11));
    }

    // layer 2: A in regs, B resident in W2s
    float acc2[16][4];
    #pragma unroll
    for (int n = 0; n < 16; n++)
        #pragma unroll
        for (int j = 0; j < 4; j++) acc2[n][j] = 0.0f;
    gemm_regA<8>(acc2, ah, W2s_b, W2s_b + 64 * SB * 2, SB, a_row, a_koff);

    // residual epilogue
    const int r0 = RW + g, r1 = RW + g + 8;
    const int nn0 = n0 + r0, nn1 = n0 + r1;
    #pragma unroll
    for (int j = 0; j < 8; j++) {
        int c0 = 16 * j + 2 * tig;
        int c1 = c0 + 8;
        if (nn0 < N) {
            out_nodes[(size_t)nn0 * 128 + c0] =
                node_feat[(size_t)nn0 * 128 + c0] + acc2[2*j][0] + nb2[c0];
            out_nodes[(size_t)nn0 * 128 + c0 + 1] =
                node_feat[(size_t)nn0 * 128 + c0 + 1] + acc2[2*j][1] + nb2[c0 + 1];
            out_nodes[(size_t)nn0 * 128 + c1] =
                node_feat[(size_t)nn0 * 128 + c1] + acc2[2*j+1][0] + nb2[c1];
            out_nodes[(size_t)nn0 * 128 + c1 + 1] =
                node_feat[(size_t)nn0 * 128 + c1 + 1] + acc2[2*j+1][1] + nb2[c1 + 1];
        }
        if (nn1 < N) {
            out_nodes[(size_t)nn1 * 128 + c0] =
                node_feat[(size_t)nn1 * 128 + c0] + acc2[2*j][2] + nb2[c0];
            out_nodes[(size_t)nn1 * 128 + c0 + 1] =
                node_feat[(size_t)nn1 * 128 + c0 + 1] + acc2[2*j][3] + nb2[c0 + 1];
            out_nodes[(size_t)nn1 * 128 + c1] =
                node_feat[(size_t)nn1 * 128 + c1] + acc2[2*j+1][2] + nb2[c1];
            out_nodes[(size_t)nn1 * 128 + c1 + 1] =
                node_feat[(size_t)nn1 * 128 + c1 + 1] + acc2[2*j+1][3] + nb2[c1 + 1];
        }
    }
    // coords
    for (int i = tid; i < 128 * 3; i += 256) {
        int e = i / 3, d = i % 3;
        int n = n0 + e;
        if (n < N)
            out_coords[(size_t)n * 3 + d] =
                coords[(size_t)n * 3 + d] + g_cacc[(size_t)n * 3 + d];
    }
    #undef N_ISSUE_A
    #undef N_ISSUE_B
}

// ---------------------------------------------------------------------------
extern "C" void kernel_launch(void* const* d_in, const int* in_sizes, int n_in,
                              void* d_out, int out_size)
{
    const float* node_feat = (const float*)d_in[0];
    const int*   eidx      = (const int*)  d_in[1];
    const float* edge_attr = (const float*)d_in[2];
    const float* coords    = (const float*)d_in[3];
    const float* eW1 = (const float*)d_in[4];
    const float* eb1 = (const float*)d_in[5];
    const float* eW2 = (const float*)d_in[6];
    const float* eb2 = (const float*)d_in[7];
    const float* nW1 = (const float*)d_in[8];
    const float* nb1 = (const float*)d_in[9];
    const float* nW2 = (const float*)d_in[10];
    const float* nb2 = (const float*)d_in[11];
    const float* cW1 = (const float*)d_in[12];
    const float* cb1 = (const float*)d_in[13];
    const float* cW2 = (const float*)d_in[14];
    const float* cb2 = (const float*)d_in[15];

    const int N = in_sizes[0] / NODE_DIM;
    const int E = in_sizes[1] / 2;
    const int* esrc = eidx;
    const int* edst = eidx + E;

    float* out_nodes  = (float*)d_out;
    float* out_coords = out_nodes + (size_t)N * NODE_DIM;

    constexpr int EDGE_SMEM = (2 * 128 * SA + 4 * 64 * SB) * 2 + 256 * 4; // 107,520 B
    constexpr int NODE_SMEM = (2 * 128 * SA + 4 * 64 * SB) * 2;          // 106,496 B
    cudaFuncSetAttribute(edge_kernel, cudaFuncAttributeMaxDynamicSharedMemorySize, EDGE_SMEM);
    cudaFuncSetAttribute(node_kernel, cudaFuncAttributeMaxDynamicSharedMemorySize, NODE_SMEM);

    prep_kernel<<<(N * NODE_DIM + 255) / 256, 256>>>(node_feat, eW1, eW2, cW1, nW1, nW2, N);

    edge_kernel<<<(E + 127) / 128, 256, EDGE_SMEM>>>(
        esrc, edst, edge_attr, coords, eb1, eb2, cb1, cW2, cb2, E);

    cvt_aggr_kernel<<<(N * HID + 255) / 256, 256>>>(N * HID);

    node_kernel<<<(N + 127) / 128, 256, NODE_SMEM>>>(
        node_feat, coords, nb1, nb2, out_nodes, out_coords, N);
}